// round 1
// baseline (speedup 1.0000x reference)
#include <cuda_runtime.h>
#include <math.h>

#define B_ 4
#define C_ 1024
#define E_ 1024
#define H_ 16
#define D_ 64
#define BCE (B_ * C_ * E_)

// Scratch: 0=K, 1=V, 2=Ku, 3=Qu, 4=Vu   (each B*C x E row-major)
__device__ float g_scr[5][B_ * C_ * E_];

// ---------------------------------------------------------------------------
// Projection GEMM: C[z] = A[z] @ W[z] + b[z]
// M=4096, N=1024, K=1024. Block tile 128x128, K-step 16, 256 thr, 8x8/thread.
// grid = (N/128, M/128, 5)
// ---------------------------------------------------------------------------
__global__ __launch_bounds__(256) void gemm_bias_kernel(
    const float* __restrict__ embed, const float* __restrict__ embed_u,
    const float* __restrict__ Wk, const float* __restrict__ Wq, const float* __restrict__ Wv,
    const float* __restrict__ bk, const float* __restrict__ bq, const float* __restrict__ bv)
{
    const int M = B_ * C_, N = E_, K = E_;
    int z = blockIdx.z;
    const float* A; const float* W; const float* bias;
    switch (z) {
        case 0:  A = embed;   W = Wk; bias = bk; break;   // K
        case 1:  A = embed;   W = Wv; bias = bv; break;   // V
        case 2:  A = embed_u; W = Wk; bias = bk; break;   // Ku
        case 3:  A = embed_u; W = Wq; bias = bq; break;   // Qu
        default: A = embed_u; W = Wv; bias = bv; break;   // Vu
    }
    float* Cout = g_scr[z];

    __shared__ float As[16][132];  // [k][m], padded
    __shared__ float Bs[16][128];  // [k][n]

    int bm = blockIdx.y * 128;
    int bn = blockIdx.x * 128;
    int t  = threadIdx.x;
    int tx = t & 15, ty = t >> 4;

    float acc[8][8];
    #pragma unroll
    for (int i = 0; i < 8; i++)
        #pragma unroll
        for (int j = 0; j < 8; j++) acc[i][j] = 0.f;

    for (int k0 = 0; k0 < K; k0 += 16) {
        // A tile: 128 rows x 16 cols = 512 float4
        #pragma unroll
        for (int l = 0; l < 2; l++) {
            int pos = t + l * 256;
            int row = pos >> 2;
            int c4  = pos & 3;
            float4 v = *(const float4*)&A[(size_t)(bm + row) * K + k0 + c4 * 4];
            As[c4 * 4 + 0][row] = v.x;
            As[c4 * 4 + 1][row] = v.y;
            As[c4 * 4 + 2][row] = v.z;
            As[c4 * 4 + 3][row] = v.w;
        }
        // B tile: 16 rows x 128 cols = 512 float4
        #pragma unroll
        for (int l = 0; l < 2; l++) {
            int pos = t + l * 256;
            int row = pos >> 5;
            int c4  = pos & 31;
            *(float4*)&Bs[row][c4 * 4] =
                *(const float4*)&W[(size_t)(k0 + row) * N + bn + c4 * 4];
        }
        __syncthreads();

        #pragma unroll
        for (int kk = 0; kk < 16; kk++) {
            float a[8], b[8];
            *(float4*)&a[0] = *(const float4*)&As[kk][ty * 8];
            *(float4*)&a[4] = *(const float4*)&As[kk][ty * 8 + 4];
            *(float4*)&b[0] = *(const float4*)&Bs[kk][tx * 8];
            *(float4*)&b[4] = *(const float4*)&Bs[kk][tx * 8 + 4];
            #pragma unroll
            for (int i = 0; i < 8; i++)
                #pragma unroll
                for (int j = 0; j < 8; j++)
                    acc[i][j] = fmaf(a[i], b[j], acc[i][j]);
        }
        __syncthreads();
    }

    #pragma unroll
    for (int i = 0; i < 8; i++) {
        int row = bm + ty * 8 + i;
        #pragma unroll
        for (int j = 0; j < 8; j += 4) {
            int col = bn + tx * 8 + j;
            float4 o;
            o.x = acc[i][j + 0] + bias[col + 0];
            o.y = acc[i][j + 1] + bias[col + 1];
            o.z = acc[i][j + 2] + bias[col + 2];
            o.w = acc[i][j + 3] + bias[col + 3];
            *(float4*)&Cout[(size_t)row * N + col] = o;
        }
    }
}

// ---------------------------------------------------------------------------
// Fused attention: one online-softmax pass produces BOTH outputs.
// CTA = (64 queries) x (one b,h). 256 threads as 16x16; thread = 4 rows x 4 cols.
// Dynamic smem: Qt[64][64] ([d][r]) + Kt[64][64] ([d][c]) + Vs[64][64] ([k][d])
//             + Ps[64][64] ([r][k], doubles as mask staging) + 4x64 row stats.
// ---------------------------------------------------------------------------
#define ATTN_SMEM ((4 * 64 * 64 + 4 * 64) * 4)

__global__ __launch_bounds__(256) void attn_kernel(
    const float* __restrict__ mask, float* __restrict__ out)
{
    extern __shared__ float sm[];
    float (*Qt)[64] = (float(*)[64])(sm);
    float (*Kt)[64] = (float(*)[64])(sm + 4096);
    float (*Vs)[64] = (float(*)[64])(sm + 8192);
    float (*Ps)[64] = (float(*)[64])(sm + 12288);
    float* row_m   = sm + 16384;
    float* row_S   = sm + 16384 + 64;
    float* row_sqq = sm + 16384 + 128;
    float* row_z   = sm + 16384 + 192;

    const float scale = 0.125f;  // 1/sqrt(64)
    int bh = blockIdx.y;
    int b = bh / H_, h = bh % H_;
    int q0 = blockIdx.x * 64;

    const float* Kp  = g_scr[0];
    const float* Vp  = g_scr[1];
    const float* Kup = g_scr[2];
    const float* Qup = g_scr[3];
    const float* Vup = g_scr[4];

    int t  = threadIdx.x;
    int tx = t & 15, ty = t >> 4;

    // Load Q tile transposed: Qt[d][r]
    #pragma unroll
    for (int l = 0; l < 4; l++) {
        int pos = t + l * 256;            // 1024 float4 positions
        int row = pos >> 4;
        int c4  = pos & 15;
        float4 v = *(const float4*)&Qup[((size_t)(b * C_ + q0 + row)) * E_ + h * 64 + c4 * 4];
        Qt[c4 * 4 + 0][row] = v.x;
        Qt[c4 * 4 + 1][row] = v.y;
        Qt[c4 * 4 + 2][row] = v.z;
        Qt[c4 * 4 + 3][row] = v.w;
    }
    if (t < 64) { row_m[t] = -1e30f; row_S[t] = 0.f; row_sqq[t] = -1e30f; }
    __syncthreads();

    // z[q] = scale * <q_u[q], k_u[q]> + mask[q][q]
    {
        int r = t >> 2, part = t & 3;
        int q = q0 + r;
        const float* ku = &Kup[((size_t)(b * C_ + q)) * E_ + h * 64];
        float s = 0.f;
        #pragma unroll
        for (int d0 = 0; d0 < 16; d0++) {
            int d = part * 16 + d0;
            s += Qt[d][r] * ku[d];
        }
        s += __shfl_xor_sync(0xffffffffu, s, 1);
        s += __shfl_xor_sync(0xffffffffu, s, 2);
        if (part == 0) row_z[r] = s * scale + mask[(size_t)q * C_ + q];
    }

    float acc[4][4];
    #pragma unroll
    for (int i = 0; i < 4; i++)
        #pragma unroll
        for (int j = 0; j < 4; j++) acc[i][j] = 0.f;

    for (int k0 = 0; k0 < C_; k0 += 64) {
        __syncthreads();  // previous iteration's consumers done

        // Load K tile (transposed), V tile, mask tile (into Ps)
        #pragma unroll
        for (int l = 0; l < 4; l++) {
            int pos = t + l * 256;
            int row = pos >> 4;
            int c4  = pos & 15;
            size_t gro = ((size_t)(b * C_ + k0 + row)) * E_ + h * 64 + c4 * 4;
            float4 kv = *(const float4*)&Kp[gro];
            Kt[c4 * 4 + 0][row] = kv.x;
            Kt[c4 * 4 + 1][row] = kv.y;
            Kt[c4 * 4 + 2][row] = kv.z;
            Kt[c4 * 4 + 3][row] = kv.w;
            *(float4*)&Vs[row][c4 * 4] = *(const float4*)&Vp[gro];
            *(float4*)&Ps[row][c4 * 4] =
                *(const float4*)&mask[(size_t)(q0 + row) * C_ + k0 + c4 * 4];
        }
        __syncthreads();

        // Scores: s[i][j] = <q_row, k_col> * scale + mask
        float s[4][4];
        #pragma unroll
        for (int i = 0; i < 4; i++)
            #pragma unroll
            for (int j = 0; j < 4; j++) s[i][j] = 0.f;

        #pragma unroll
        for (int d = 0; d < 64; d++) {
            float4 qa = *(const float4*)&Qt[d][ty * 4];
            float4 kb = *(const float4*)&Kt[d][tx * 4];
            float qs[4] = {qa.x, qa.y, qa.z, qa.w};
            float ks[4] = {kb.x, kb.y, kb.z, kb.w};
            #pragma unroll
            for (int i = 0; i < 4; i++)
                #pragma unroll
                for (int j = 0; j < 4; j++)
                    s[i][j] = fmaf(qs[i], ks[j], s[i][j]);
        }
        #pragma unroll
        for (int i = 0; i < 4; i++)
            #pragma unroll
            for (int j = 0; j < 4; j++)
                s[i][j] = s[i][j] * scale + Ps[ty * 4 + i][tx * 4 + j];

        // Online softmax per row
        #pragma unroll
        for (int i = 0; i < 4; i++) {
            int r = ty * 4 + i;
            float mt = fmaxf(fmaxf(s[i][0], s[i][1]), fmaxf(s[i][2], s[i][3]));
            mt = fmaxf(mt, __shfl_xor_sync(0xffffffffu, mt, 1));
            mt = fmaxf(mt, __shfl_xor_sync(0xffffffffu, mt, 2));
            mt = fmaxf(mt, __shfl_xor_sync(0xffffffffu, mt, 4));
            mt = fmaxf(mt, __shfl_xor_sync(0xffffffffu, mt, 8));

            float m_old = row_m[r];
            float m_new = fmaxf(m_old, mt);
            float al = __expf(m_old - m_new);

            float p[4];
            float psum = 0.f;
            #pragma unroll
            for (int j = 0; j < 4; j++) {
                p[j] = __expf(s[i][j] - m_new);
                psum += p[j];
                if (k0 + tx * 4 + j == q0 + r) row_sqq[r] = s[i][j];  // raw diag score
            }
            psum += __shfl_xor_sync(0xffffffffu, psum, 1);
            psum += __shfl_xor_sync(0xffffffffu, psum, 2);
            psum += __shfl_xor_sync(0xffffffffu, psum, 4);
            psum += __shfl_xor_sync(0xffffffffu, psum, 8);
            // shfl_sync above converges the warp: reads of row_m/row_S done before write
            if (tx == 0) { row_S[r] = row_S[r] * al + psum; row_m[r] = m_new; }

            #pragma unroll
            for (int j = 0; j < 4; j++) acc[i][j] *= al;

            *(float4*)&Ps[r][tx * 4] = make_float4(p[0], p[1], p[2], p[3]);
        }
        __syncthreads();

        // PV: acc[i][j] += sum_k Ps[r][k] * Vs[k][d]
        #pragma unroll
        for (int k = 0; k < 64; k++) {
            float4 vv = *(const float4*)&Vs[k][tx * 4];
            #pragma unroll
            for (int i = 0; i < 4; i++) {
                float pp = Ps[ty * 4 + i][k];
                acc[i][0] = fmaf(pp, vv.x, acc[i][0]);
                acc[i][1] = fmaf(pp, vv.y, acc[i][1]);
                acc[i][2] = fmaf(pp, vv.z, acc[i][2]);
                acc[i][3] = fmaf(pp, vv.w, acc[i][3]);
            }
        }
    }
    __syncthreads();

    // Epilogue: both outputs from one accumulation
    #pragma unroll
    for (int i = 0; i < 4; i++) {
        int r = ty * 4 + i;
        int q = q0 + r;
        float m_f  = row_m[r];
        float S    = row_S[r];
        float e_qq = __expf(row_sqq[r] - m_f);
        float e_z  = __expf(row_z[r]  - m_f);
        float Su   = S - e_qq + e_z;
        float invS = 1.f / S, invSu = 1.f / Su;

        size_t go = ((size_t)(b * C_ + q)) * E_ + h * 64 + tx * 4;
        float4 vq = *(const float4*)&Vp[go];
        float4 vu = *(const float4*)&Vup[go];

        float4 o, ou;
        o.x = acc[i][0] * invS;
        o.y = acc[i][1] * invS;
        o.z = acc[i][2] * invS;
        o.w = acc[i][3] * invS;
        ou.x = (acc[i][0] - e_qq * vq.x + e_z * vu.x) * invSu;
        ou.y = (acc[i][1] - e_qq * vq.y + e_z * vu.y) * invSu;
        ou.z = (acc[i][2] - e_qq * vq.z + e_z * vu.z) * invSu;
        ou.w = (acc[i][3] - e_qq * vq.w + e_z * vu.w) * invSu;

        *(float4*)&out[go]              = o;
        *(float4*)&out[(size_t)BCE + go] = ou;
    }
}

// ---------------------------------------------------------------------------
extern "C" void kernel_launch(void* const* d_in, const int* in_sizes, int n_in,
                              void* d_out, int out_size)
{
    const float* embed   = (const float*)d_in[0];
    const float* embed_u = (const float*)d_in[1];
    const float* mask    = (const float*)d_in[2];
    const float* Wk      = (const float*)d_in[3];
    const float* bk      = (const float*)d_in[4];
    const float* Wq      = (const float*)d_in[5];
    const float* bq      = (const float*)d_in[6];
    const float* Wv      = (const float*)d_in[7];
    const float* bv      = (const float*)d_in[8];
    float* out = (float*)d_out;

    dim3 gb(E_ / 128, (B_ * C_) / 128, 5);
    gemm_bias_kernel<<<gb, 256>>>(embed, embed_u, Wk, Wq, Wv, bk, bq, bv);

    cudaFuncSetAttribute(attn_kernel, cudaFuncAttributeMaxDynamicSharedMemorySize, ATTN_SMEM);
    dim3 ga(C_ / 64, B_ * H_);
    attn_kernel<<<ga, 256, ATTN_SMEM>>>(mask, out);
}

// round 4
// speedup vs baseline: 1.5535x; 1.5535x over previous
#include <cuda_runtime.h>
#include <cuda_bf16.h>
#include <math.h>
#include <stdint.h>

#define B_ 4
#define C_ 1024
#define E_ 1024
#define H_ 16
#define D_ 64
#define BCE (B_ * C_ * E_)

// Scratch: 0=K, 1=V, 2=Ku, 3=Qu, 4=Vu   (each B*C x E row-major)
__device__ float g_scr[5][B_ * C_ * E_];

// ===========================================================================
// mma.sync bf16 split-precision GEMM:  C[z] = A[z] @ W[z] + b[z]
// M=4096 N=1024 K=1024 x5. CTA tile 128x128, K-chunk 32, 8 warps (64x32 each).
// x = hi + lo (bf16); acc += Ahi*Bhi + Alo*Bhi + Ahi*Blo  (fp32 accum).
// smem rows padded to 80B: 8 consecutive rows -> 8 distinct 16B banks => LDSM
// conflict-free without swizzle.
// ===========================================================================
#define ROWB 80                     // bytes per smem row (32 bf16 + 8 pad)
#define A_HI 0
#define A_LO 10240
#define B_HI 20480
#define B_LO 30720
#define GEMM_SMEM_BYTES 40960

__device__ __forceinline__ uint32_t smem_u32(const void* p) {
    uint32_t a;
    asm("{ .reg .u64 t; cvta.to.shared.u64 t, %1; cvt.u32.u64 %0, t; }"
        : "=r"(a) : "l"(p));
    return a;
}
__device__ __forceinline__ void ldsm4(uint32_t& r0, uint32_t& r1, uint32_t& r2,
                                      uint32_t& r3, uint32_t addr) {
    asm volatile("ldmatrix.sync.aligned.m8n8.x4.shared.b16 {%0,%1,%2,%3}, [%4];"
                 : "=r"(r0), "=r"(r1), "=r"(r2), "=r"(r3) : "r"(addr));
}
__device__ __forceinline__ void mma_bf16(float* d, const uint32_t* a, const uint32_t* b) {
    asm volatile(
        "mma.sync.aligned.m16n8k16.row.col.f32.bf16.bf16.f32 "
        "{%0,%1,%2,%3}, {%4,%5,%6,%7}, {%8,%9}, {%0,%1,%2,%3};"
        : "+f"(d[0]), "+f"(d[1]), "+f"(d[2]), "+f"(d[3])
        : "r"(a[0]), "r"(a[1]), "r"(a[2]), "r"(a[3]), "r"(b[0]), "r"(b[1]));
}
__device__ __forceinline__ uint32_t pack_bf16(float x, float y) {
    __nv_bfloat162 h = __floats2bfloat162_rn(x, y);
    return *(uint32_t*)&h;
}

__global__ __launch_bounds__(256, 2) void gemm_tc_kernel(
    const float* __restrict__ embed, const float* __restrict__ embed_u,
    const float* __restrict__ Wk, const float* __restrict__ Wq, const float* __restrict__ Wv,
    const float* __restrict__ bk, const float* __restrict__ bq, const float* __restrict__ bv)
{
    __shared__ __align__(1024) char gsm[GEMM_SMEM_BYTES];

    const int N = E_, K = E_;
    int z = blockIdx.z;
    const float* A; const float* W; const float* bias;
    switch (z) {
        case 0:  A = embed;   W = Wk; bias = bk; break;   // K
        case 1:  A = embed;   W = Wv; bias = bv; break;   // V
        case 2:  A = embed_u; W = Wk; bias = bk; break;   // Ku
        case 3:  A = embed_u; W = Wq; bias = bq; break;   // Qu
        default: A = embed_u; W = Wv; bias = bv; break;   // Vu
    }
    float* Cout = g_scr[z];

    int t = threadIdx.x;
    int lane = t & 31, warp = t >> 5;
    int wm = warp & 1, wn = warp >> 1;        // warp tile: (wm*64, wn*32)
    int bm = blockIdx.y * 128;
    int bn = blockIdx.x * 128;

    uint32_t sb = smem_u32(gsm);

    // LDSM lane addressing (conflict-free via 80B row stride)
    int a_row_l = lane & 15;
    int a_kb_l  = (lane >> 4) * 16;
    int b_row_l = (lane & 7) + ((lane >> 4) & 1) * 8;
    int b_kb_l  = ((lane >> 3) & 1) * 16;

    uint32_t aAddr[4], bAddr[2];
    #pragma unroll
    for (int mf = 0; mf < 4; mf++)
        aAddr[mf] = sb + (uint32_t)((wm * 64 + mf * 16 + a_row_l) * ROWB + a_kb_l);
    #pragma unroll
    for (int p = 0; p < 2; p++)
        bAddr[p] = sb + (uint32_t)(B_HI + (wn * 32 + p * 16 + b_row_l) * ROWB + b_kb_l);

    float acc[4][4][4];
    #pragma unroll
    for (int i = 0; i < 4; i++)
        #pragma unroll
        for (int j = 0; j < 4; j++)
            #pragma unroll
            for (int q = 0; q < 4; q++) acc[i][j][q] = 0.f;

    for (int c = 0; c < K / 32; c++) {
        int k0 = c * 32;
        __syncthreads();
        // ---- load chunk: A [128m x 32k], split hi/lo ----
        #pragma unroll
        for (int i = 0; i < 4; i++) {
            int id = t + i * 256;
            int c4 = id & 7, row = id >> 3;
            float4 v = *(const float4*)&A[(size_t)(bm + row) * K + k0 + c4 * 4];
            uint32_t h0 = pack_bf16(v.x, v.y), h1 = pack_bf16(v.z, v.w);
            float lx = v.x - __bfloat162float(((__nv_bfloat162*)&h0)->x);
            float ly = v.y - __bfloat162float(((__nv_bfloat162*)&h0)->y);
            float lz = v.z - __bfloat162float(((__nv_bfloat162*)&h1)->x);
            float lw = v.w - __bfloat162float(((__nv_bfloat162*)&h1)->y);
            uint32_t l0 = pack_bf16(lx, ly), l1 = pack_bf16(lz, lw);
            int off = row * ROWB + c4 * 8;
            *(uint2*)(gsm + A_HI + off) = make_uint2(h0, h1);
            *(uint2*)(gsm + A_LO + off) = make_uint2(l0, l1);
        }
        // ---- load chunk: B = W[k0:32][bn:128] transposed -> [n][k] ----
        #pragma unroll
        for (int i = 0; i < 4; i++) {
            int id = t + i * 256;
            int n = id & 127, kb = id >> 7;
            const float* wp = &W[(size_t)(k0 + kb * 4) * N + bn + n];
            float w0 = wp[0], w1 = wp[N], w2 = wp[2 * N], w3 = wp[3 * N];
            uint32_t h0 = pack_bf16(w0, w1), h1 = pack_bf16(w2, w3);
            float l0f = w0 - __bfloat162float(((__nv_bfloat162*)&h0)->x);
            float l1f = w1 - __bfloat162float(((__nv_bfloat162*)&h0)->y);
            float l2f = w2 - __bfloat162float(((__nv_bfloat162*)&h1)->x);
            float l3f = w3 - __bfloat162float(((__nv_bfloat162*)&h1)->y);
            uint32_t l0 = pack_bf16(l0f, l1f), l1 = pack_bf16(l2f, l3f);
            int off = n * ROWB + kb * 8;
            *(uint2*)(gsm + B_HI + off) = make_uint2(h0, h1);
            *(uint2*)(gsm + B_LO + off) = make_uint2(l0, l1);
        }
        __syncthreads();

        // ---- compute: two k16 halves ----
        #pragma unroll
        for (int kb = 0; kb < 64; kb += 32) {
            uint32_t a[4][4], b[4][2];
            // term 1: Ahi * Bhi
            #pragma unroll
            for (int p = 0; p < 2; p++)
                ldsm4(b[2 * p][0], b[2 * p][1], b[2 * p + 1][0], b[2 * p + 1][1],
                      bAddr[p] + kb);
            #pragma unroll
            for (int mf = 0; mf < 4; mf++)
                ldsm4(a[mf][0], a[mf][1], a[mf][2], a[mf][3], aAddr[mf] + kb);
            #pragma unroll
            for (int mf = 0; mf < 4; mf++)
                #pragma unroll
                for (int nf = 0; nf < 4; nf++) mma_bf16(acc[mf][nf], a[mf], b[nf]);
            // term 2: Alo * Bhi
            #pragma unroll
            for (int mf = 0; mf < 4; mf++)
                ldsm4(a[mf][0], a[mf][1], a[mf][2], a[mf][3], aAddr[mf] + A_LO + kb);
            #pragma unroll
            for (int mf = 0; mf < 4; mf++)
                #pragma unroll
                for (int nf = 0; nf < 4; nf++) mma_bf16(acc[mf][nf], a[mf], b[nf]);
            // term 3: Ahi * Blo
            #pragma unroll
            for (int p = 0; p < 2; p++)
                ldsm4(b[2 * p][0], b[2 * p][1], b[2 * p + 1][0], b[2 * p + 1][1],
                      bAddr[p] + 10240 + kb);        // B_LO - B_HI = 10240
            #pragma unroll
            for (int mf = 0; mf < 4; mf++)
                ldsm4(a[mf][0], a[mf][1], a[mf][2], a[mf][3], aAddr[mf] + kb);
            #pragma unroll
            for (int mf = 0; mf < 4; mf++)
                #pragma unroll
                for (int nf = 0; nf < 4; nf++) mma_bf16(acc[mf][nf], a[mf], b[nf]);
        }
    }

    // ---- epilogue: acc + bias -> gmem ----
    #pragma unroll
    for (int mf = 0; mf < 4; mf++) {
        int row0 = bm + wm * 64 + mf * 16 + (lane >> 2);
        #pragma unroll
        for (int nf = 0; nf < 4; nf++) {
            int col = bn + wn * 32 + nf * 8 + (lane & 3) * 2;
            float2 bv2 = *(const float2*)&bias[col];
            float2 o0 = make_float2(acc[mf][nf][0] + bv2.x, acc[mf][nf][1] + bv2.y);
            float2 o1 = make_float2(acc[mf][nf][2] + bv2.x, acc[mf][nf][3] + bv2.y);
            *(float2*)&Cout[(size_t)row0 * N + col]       = o0;
            *(float2*)&Cout[(size_t)(row0 + 8) * N + col] = o1;
        }
    }
}

// ---------------------------------------------------------------------------
// Fused attention (unchanged, known-good): one online-softmax pass -> BOTH outs.
// ---------------------------------------------------------------------------
#define ATTN_SMEM ((4 * 64 * 64 + 4 * 64) * 4)

__global__ __launch_bounds__(256) void attn_kernel(
    const float* __restrict__ mask, float* __restrict__ out)
{
    extern __shared__ float sm[];
    float (*Qt)[64] = (float(*)[64])(sm);
    float (*Kt)[64] = (float(*)[64])(sm + 4096);
    float (*Vs)[64] = (float(*)[64])(sm + 8192);
    float (*Ps)[64] = (float(*)[64])(sm + 12288);
    float* row_m   = sm + 16384;
    float* row_S   = sm + 16384 + 64;
    float* row_sqq = sm + 16384 + 128;
    float* row_z   = sm + 16384 + 192;

    const float scale = 0.125f;
    int bh = blockIdx.y;
    int b = bh / H_, h = bh % H_;
    int q0 = blockIdx.x * 64;

    const float* Kp  = g_scr[0];
    const float* Vp  = g_scr[1];
    const float* Kup = g_scr[2];
    const float* Qup = g_scr[3];
    const float* Vup = g_scr[4];

    int t  = threadIdx.x;
    int tx = t & 15, ty = t >> 4;

    #pragma unroll
    for (int l = 0; l < 4; l++) {
        int pos = t + l * 256;
        int row = pos >> 4;
        int c4  = pos & 15;
        float4 v = *(const float4*)&Qup[((size_t)(b * C_ + q0 + row)) * E_ + h * 64 + c4 * 4];
        Qt[c4 * 4 + 0][row] = v.x;
        Qt[c4 * 4 + 1][row] = v.y;
        Qt[c4 * 4 + 2][row] = v.z;
        Qt[c4 * 4 + 3][row] = v.w;
    }
    if (t < 64) { row_m[t] = -1e30f; row_S[t] = 0.f; row_sqq[t] = -1e30f; }
    __syncthreads();

    {
        int r = t >> 2, part = t & 3;
        int q = q0 + r;
        const float* ku = &Kup[((size_t)(b * C_ + q)) * E_ + h * 64];
        float s = 0.f;
        #pragma unroll
        for (int d0 = 0; d0 < 16; d0++) {
            int d = part * 16 + d0;
            s += Qt[d][r] * ku[d];
        }
        s += __shfl_xor_sync(0xffffffffu, s, 1);
        s += __shfl_xor_sync(0xffffffffu, s, 2);
        if (part == 0) row_z[r] = s * scale + mask[(size_t)q * C_ + q];
    }

    float acc[4][4];
    #pragma unroll
    for (int i = 0; i < 4; i++)
        #pragma unroll
        for (int j = 0; j < 4; j++) acc[i][j] = 0.f;

    for (int k0 = 0; k0 < C_; k0 += 64) {
        __syncthreads();

        #pragma unroll
        for (int l = 0; l < 4; l++) {
            int pos = t + l * 256;
            int row = pos >> 4;
            int c4  = pos & 15;
            size_t gro = ((size_t)(b * C_ + k0 + row)) * E_ + h * 64 + c4 * 4;
            float4 kv = *(const float4*)&Kp[gro];
            Kt[c4 * 4 + 0][row] = kv.x;
            Kt[c4 * 4 + 1][row] = kv.y;
            Kt[c4 * 4 + 2][row] = kv.z;
            Kt[c4 * 4 + 3][row] = kv.w;
            *(float4*)&Vs[row][c4 * 4] = *(const float4*)&Vp[gro];
            *(float4*)&Ps[row][c4 * 4] =
                *(const float4*)&mask[(size_t)(q0 + row) * C_ + k0 + c4 * 4];
        }
        __syncthreads();

        float s[4][4];
        #pragma unroll
        for (int i = 0; i < 4; i++)
            #pragma unroll
            for (int j = 0; j < 4; j++) s[i][j] = 0.f;

        #pragma unroll
        for (int d = 0; d < 64; d++) {
            float4 qa = *(const float4*)&Qt[d][ty * 4];
            float4 kb = *(const float4*)&Kt[d][tx * 4];
            float qs[4] = {qa.x, qa.y, qa.z, qa.w};
            float ks[4] = {kb.x, kb.y, kb.z, kb.w};
            #pragma unroll
            for (int i = 0; i < 4; i++)
                #pragma unroll
                for (int j = 0; j < 4; j++)
                    s[i][j] = fmaf(qs[i], ks[j], s[i][j]);
        }
        #pragma unroll
        for (int i = 0; i < 4; i++)
            #pragma unroll
            for (int j = 0; j < 4; j++)
                s[i][j] = s[i][j] * scale + Ps[ty * 4 + i][tx * 4 + j];

        #pragma unroll
        for (int i = 0; i < 4; i++) {
            int r = ty * 4 + i;
            float mt = fmaxf(fmaxf(s[i][0], s[i][1]), fmaxf(s[i][2], s[i][3]));
            mt = fmaxf(mt, __shfl_xor_sync(0xffffffffu, mt, 1));
            mt = fmaxf(mt, __shfl_xor_sync(0xffffffffu, mt, 2));
            mt = fmaxf(mt, __shfl_xor_sync(0xffffffffu, mt, 4));
            mt = fmaxf(mt, __shfl_xor_sync(0xffffffffu, mt, 8));

            float m_old = row_m[r];
            float m_new = fmaxf(m_old, mt);
            float al = __expf(m_old - m_new);

            float p[4];
            float psum = 0.f;
            #pragma unroll
            for (int j = 0; j < 4; j++) {
                p[j] = __expf(s[i][j] - m_new);
                psum += p[j];
                if (k0 + tx * 4 + j == q0 + r) row_sqq[r] = s[i][j];
            }
            psum += __shfl_xor_sync(0xffffffffu, psum, 1);
            psum += __shfl_xor_sync(0xffffffffu, psum, 2);
            psum += __shfl_xor_sync(0xffffffffu, psum, 4);
            psum += __shfl_xor_sync(0xffffffffu, psum, 8);
            if (tx == 0) { row_S[r] = row_S[r] * al + psum; row_m[r] = m_new; }

            #pragma unroll
            for (int j = 0; j < 4; j++) acc[i][j] *= al;

            *(float4*)&Ps[r][tx * 4] = make_float4(p[0], p[1], p[2], p[3]);
        }
        __syncthreads();

        #pragma unroll
        for (int k = 0; k < 64; k++) {
            float4 vv = *(const float4*)&Vs[k][tx * 4];
            #pragma unroll
            for (int i = 0; i < 4; i++) {
                float pp = Ps[ty * 4 + i][k];
                acc[i][0] = fmaf(pp, vv.x, acc[i][0]);
                acc[i][1] = fmaf(pp, vv.y, acc[i][1]);
                acc[i][2] = fmaf(pp, vv.z, acc[i][2]);
                acc[i][3] = fmaf(pp, vv.w, acc[i][3]);
            }
        }
    }
    __syncthreads();

    #pragma unroll
    for (int i = 0; i < 4; i++) {
        int r = ty * 4 + i;
        int q = q0 + r;
        float m_f  = row_m[r];
        float S    = row_S[r];
        float e_qq = __expf(row_sqq[r] - m_f);
        float e_z  = __expf(row_z[r]  - m_f);
        float Su   = S - e_qq + e_z;
        float invS = 1.f / S, invSu = 1.f / Su;

        size_t go = ((size_t)(b * C_ + q)) * E_ + h * 64 + tx * 4;
        float4 vq = *(const float4*)&Vp[go];
        float4 vu = *(const float4*)&Vup[go];

        float4 o, ou;
        o.x = acc[i][0] * invS;
        o.y = acc[i][1] * invS;
        o.z = acc[i][2] * invS;
        o.w = acc[i][3] * invS;
        ou.x = (acc[i][0] - e_qq * vq.x + e_z * vu.x) * invSu;
        ou.y = (acc[i][1] - e_qq * vq.y + e_z * vu.y) * invSu;
        ou.z = (acc[i][2] - e_qq * vq.z + e_z * vu.z) * invSu;
        ou.w = (acc[i][3] - e_qq * vq.w + e_z * vu.w) * invSu;

        *(float4*)&out[go]               = o;
        *(float4*)&out[(size_t)BCE + go] = ou;
    }
}

// ---------------------------------------------------------------------------
extern "C" void kernel_launch(void* const* d_in, const int* in_sizes, int n_in,
                              void* d_out, int out_size)
{
    const float* embed   = (const float*)d_in[0];
    const float* embed_u = (const float*)d_in[1];
    const float* mask    = (const float*)d_in[2];
    const float* Wk      = (const float*)d_in[3];
    const float* bk      = (const float*)d_in[4];
    const float* Wq      = (const float*)d_in[5];
    const float* bq      = (const float*)d_in[6];
    const float* Wv      = (const float*)d_in[7];
    const float* bv      = (const float*)d_in[8];
    float* out = (float*)d_out;

    dim3 gg(E_ / 128, (B_ * C_) / 128, 5);
    gemm_tc_kernel<<<gg, 256>>>(embed, embed_u, Wk, Wq, Wv, bk, bq, bv);

    cudaFuncSetAttribute(attn_kernel, cudaFuncAttributeMaxDynamicSharedMemorySize, ATTN_SMEM);
    dim3 ga(C_ / 64, B_ * H_);
    attn_kernel<<<ga, 256, ATTN_SMEM>>>(mask, out);
}

// round 7
// speedup vs baseline: 2.6106x; 1.6804x over previous
#include <cuda_runtime.h>
#include <cuda_bf16.h>
#include <math.h>
#include <stdint.h>

#define B_ 4
#define C_ 1024
#define E_ 1024
#define H_ 16
#define D_ 64
#define BCE (B_ * C_ * E_)

// Scratch: 0=K, 1=V, 2=Ku, 3=Qu, 4=Vu   (each B*C x E row-major)
__device__ float g_scr[5][B_ * C_ * E_];

// ---------------------------------------------------------------------------
// Common helpers
// ---------------------------------------------------------------------------
__device__ __forceinline__ uint32_t smem_u32(const void* p) {
    uint32_t a;
    asm("{ .reg .u64 t; cvta.to.shared.u64 t, %1; cvt.u32.u64 %0, t; }"
        : "=r"(a) : "l"(p));
    return a;
}
__device__ __forceinline__ void ldsm4(uint32_t& r0, uint32_t& r1, uint32_t& r2,
                                      uint32_t& r3, uint32_t addr) {
    asm volatile("ldmatrix.sync.aligned.m8n8.x4.shared.b16 {%0,%1,%2,%3}, [%4];"
                 : "=r"(r0), "=r"(r1), "=r"(r2), "=r"(r3) : "r"(addr));
}
__device__ __forceinline__ void ldsm4t(uint32_t& r0, uint32_t& r1, uint32_t& r2,
                                       uint32_t& r3, uint32_t addr) {
    asm volatile("ldmatrix.sync.aligned.m8n8.x4.trans.shared.b16 {%0,%1,%2,%3}, [%4];"
                 : "=r"(r0), "=r"(r1), "=r"(r2), "=r"(r3) : "r"(addr));
}
__device__ __forceinline__ void mma_bf16(float* d, const uint32_t* a, const uint32_t* b) {
    asm volatile(
        "mma.sync.aligned.m16n8k16.row.col.f32.bf16.bf16.f32 "
        "{%0,%1,%2,%3}, {%4,%5,%6,%7}, {%8,%9}, {%0,%1,%2,%3};"
        : "+f"(d[0]), "+f"(d[1]), "+f"(d[2]), "+f"(d[3])
        : "r"(a[0]), "r"(a[1]), "r"(a[2]), "r"(a[3]), "r"(b[0]), "r"(b[1]));
}
__device__ __forceinline__ uint32_t pack_bf16(float x, float y) {
    __nv_bfloat162 h = __floats2bfloat162_rn(x, y);
    return *(uint32_t*)&h;
}
__device__ __forceinline__ void split2(float x, float y, uint32_t& hi, uint32_t& lo) {
    __nv_bfloat162 h = __floats2bfloat162_rn(x, y);
    hi = *(uint32_t*)&h;
    float lx = x - __bfloat162float(h.x);
    float ly = y - __bfloat162float(h.y);
    __nv_bfloat162 l = __floats2bfloat162_rn(lx, ly);
    lo = *(uint32_t*)&l;
}

// ===========================================================================
// mma.sync bf16 split-precision GEMM (unchanged, known-good)
// ===========================================================================
#define ROWB 80
#define A_HI 0
#define A_LO 10240
#define B_HI 20480
#define B_LO 30720
#define GEMM_SMEM_BYTES 40960

__global__ __launch_bounds__(256, 2) void gemm_tc_kernel(
    const float* __restrict__ embed, const float* __restrict__ embed_u,
    const float* __restrict__ Wk, const float* __restrict__ Wq, const float* __restrict__ Wv,
    const float* __restrict__ bk, const float* __restrict__ bq, const float* __restrict__ bv)
{
    __shared__ __align__(1024) char gsm[GEMM_SMEM_BYTES];

    const int N = E_, K = E_;
    int z = blockIdx.z;
    const float* A; const float* W; const float* bias;
    switch (z) {
        case 0:  A = embed;   W = Wk; bias = bk; break;
        case 1:  A = embed;   W = Wv; bias = bv; break;
        case 2:  A = embed_u; W = Wk; bias = bk; break;
        case 3:  A = embed_u; W = Wq; bias = bq; break;
        default: A = embed_u; W = Wv; bias = bv; break;
    }
    float* Cout = g_scr[z];

    int t = threadIdx.x;
    int lane = t & 31, warp = t >> 5;
    int wm = warp & 1, wn = warp >> 1;
    int bm = blockIdx.y * 128;
    int bn = blockIdx.x * 128;

    uint32_t sb = smem_u32(gsm);

    int a_row_l = lane & 15;
    int a_kb_l  = (lane >> 4) * 16;
    int b_row_l = (lane & 7) + ((lane >> 4) & 1) * 8;
    int b_kb_l  = ((lane >> 3) & 1) * 16;

    uint32_t aAddr[4], bAddr[2];
    #pragma unroll
    for (int mf = 0; mf < 4; mf++)
        aAddr[mf] = sb + (uint32_t)((wm * 64 + mf * 16 + a_row_l) * ROWB + a_kb_l);
    #pragma unroll
    for (int p = 0; p < 2; p++)
        bAddr[p] = sb + (uint32_t)(B_HI + (wn * 32 + p * 16 + b_row_l) * ROWB + b_kb_l);

    float acc[4][4][4];
    #pragma unroll
    for (int i = 0; i < 4; i++)
        #pragma unroll
        for (int j = 0; j < 4; j++)
            #pragma unroll
            for (int q = 0; q < 4; q++) acc[i][j][q] = 0.f;

    for (int c = 0; c < K / 32; c++) {
        int k0 = c * 32;
        __syncthreads();
        #pragma unroll
        for (int i = 0; i < 4; i++) {
            int id = t + i * 256;
            int c4 = id & 7, row = id >> 3;
            float4 v = *(const float4*)&A[(size_t)(bm + row) * K + k0 + c4 * 4];
            uint32_t h0, l0, h1, l1;
            split2(v.x, v.y, h0, l0);
            split2(v.z, v.w, h1, l1);
            int off = row * ROWB + c4 * 8;
            *(uint2*)(gsm + A_HI + off) = make_uint2(h0, h1);
            *(uint2*)(gsm + A_LO + off) = make_uint2(l0, l1);
        }
        #pragma unroll
        for (int i = 0; i < 4; i++) {
            int id = t + i * 256;
            int n = id & 127, kb = id >> 7;
            const float* wp = &W[(size_t)(k0 + kb * 4) * N + bn + n];
            float w0 = wp[0], w1 = wp[N], w2 = wp[2 * N], w3 = wp[3 * N];
            uint32_t h0, l0, h1, l1;
            split2(w0, w1, h0, l0);
            split2(w2, w3, h1, l1);
            int off = n * ROWB + kb * 8;
            *(uint2*)(gsm + B_HI + off) = make_uint2(h0, h1);
            *(uint2*)(gsm + B_LO + off) = make_uint2(l0, l1);
        }
        __syncthreads();

        #pragma unroll
        for (int kb = 0; kb < 64; kb += 32) {
            uint32_t a[4][4], b[4][2];
            #pragma unroll
            for (int p = 0; p < 2; p++)
                ldsm4(b[2 * p][0], b[2 * p][1], b[2 * p + 1][0], b[2 * p + 1][1],
                      bAddr[p] + kb);
            #pragma unroll
            for (int mf = 0; mf < 4; mf++)
                ldsm4(a[mf][0], a[mf][1], a[mf][2], a[mf][3], aAddr[mf] + kb);
            #pragma unroll
            for (int mf = 0; mf < 4; mf++)
                #pragma unroll
                for (int nf = 0; nf < 4; nf++) mma_bf16(acc[mf][nf], a[mf], b[nf]);
            #pragma unroll
            for (int mf = 0; mf < 4; mf++)
                ldsm4(a[mf][0], a[mf][1], a[mf][2], a[mf][3], aAddr[mf] + A_LO + kb);
            #pragma unroll
            for (int mf = 0; mf < 4; mf++)
                #pragma unroll
                for (int nf = 0; nf < 4; nf++) mma_bf16(acc[mf][nf], a[mf], b[nf]);
            #pragma unroll
            for (int p = 0; p < 2; p++)
                ldsm4(b[2 * p][0], b[2 * p][1], b[2 * p + 1][0], b[2 * p + 1][1],
                      bAddr[p] + 10240 + kb);
            #pragma unroll
            for (int mf = 0; mf < 4; mf++)
                ldsm4(a[mf][0], a[mf][1], a[mf][2], a[mf][3], aAddr[mf] + kb);
            #pragma unroll
            for (int mf = 0; mf < 4; mf++)
                #pragma unroll
                for (int nf = 0; nf < 4; nf++) mma_bf16(acc[mf][nf], a[mf], b[nf]);
        }
    }

    #pragma unroll
    for (int mf = 0; mf < 4; mf++) {
        int row0 = bm + wm * 64 + mf * 16 + (lane >> 2);
        #pragma unroll
        for (int nf = 0; nf < 4; nf++) {
            int col = bn + wn * 32 + nf * 8 + (lane & 3) * 2;
            float2 bv2 = *(const float2*)&bias[col];
            float2 o0 = make_float2(acc[mf][nf][0] + bv2.x, acc[mf][nf][1] + bv2.y);
            float2 o1 = make_float2(acc[mf][nf][2] + bv2.x, acc[mf][nf][3] + bv2.y);
            *(float2*)&Cout[(size_t)row0 * N + col]       = o0;
            *(float2*)&Cout[(size_t)(row0 + 8) * N + col] = o1;
        }
    }
}

// ===========================================================================
// Tensor-core attention: split-bf16 QK^T and PV, online softmax on fragments.
// CTA = 128 queries x one (b,h). 8 warps, warp = m16 row block.
// Key tiles of 64. Both outputs from one accumulation (diag-swap identity).
// ===========================================================================
#define AROW 144          // 64 bf16 (128B) + 16B pad: LDSM conflict-free
#define S_QHI 0
#define S_QLO 18432
#define S_KHI 36864
#define S_KLO 46080
#define S_VHI 55296
#define S_VLO 64512
#define S_RZ  73728
#define ATTN_SMEM_B (73728 + 512)

__global__ __launch_bounds__(256) void attn_tc_kernel(
    const float* __restrict__ mask, float* __restrict__ out)
{
    extern __shared__ __align__(1024) char smb[];
    uint32_t sb = smem_u32(smb);
    float* rowz = (float*)(smb + S_RZ);

    const float scale = 0.125f;
    int t = threadIdx.x, lane = t & 31, warp = t >> 5;
    int bh = blockIdx.y, b = bh >> 4, h = bh & 15;
    int q0 = blockIdx.x * 128;

    const float* Kp  = g_scr[0];
    const float* Vp  = g_scr[1];
    const float* Kup = g_scr[2];
    const float* Qup = g_scr[3];
    const float* Vup = g_scr[4];

    // ---- Q tile (128x64) -> smem hi/lo ----
    #pragma unroll
    for (int i = 0; i < 8; i++) {
        int id = t + i * 256;            // 2048 float4 positions
        int row = id >> 4, c4 = id & 15;
        float4 v = *(const float4*)&Qup[((size_t)(b * C_ + q0 + row)) * E_ + h * 64 + c4 * 4];
        uint32_t h0, l0, h1, l1;
        split2(v.x, v.y, h0, l0);
        split2(v.z, v.w, h1, l1);
        int off = row * AROW + c4 * 8;
        *(uint2*)(smb + S_QHI + off) = make_uint2(h0, h1);
        *(uint2*)(smb + S_QLO + off) = make_uint2(l0, l1);
    }
    // ---- z[q] = scale*<q_u,k_u> + mask[q][q] ----
    {
        int row = t >> 1, part = t & 1;
        int q = q0 + row;
        const float* qp = &Qup[((size_t)(b * C_ + q)) * E_ + h * 64 + part * 32];
        const float* kp = &Kup[((size_t)(b * C_ + q)) * E_ + h * 64 + part * 32];
        float s = 0.f;
        #pragma unroll
        for (int i = 0; i < 8; i++) {
            float4 a = *(const float4*)&qp[i * 4];
            float4 c = *(const float4*)&kp[i * 4];
            s += a.x * c.x + a.y * c.y + a.z * c.z + a.w * c.w;
        }
        s += __shfl_xor_sync(0xffffffffu, s, 1);
        if (part == 0) rowz[row] = s * scale + mask[(size_t)q * C_ + q];
    }
    __syncthreads();

    int wrow = warp * 16;
    int qr = lane >> 2;                      // 0..7
    int qrow_g = q0 + wrow + qr;             // global row (half 0); half1 = +8

    // ldmatrix addresses (AROW=144 stride is conflict-free)
    uint32_t aQhi = sb + S_QHI + (uint32_t)((wrow + (lane & 15)) * AROW + (lane >> 4) * 16);
    uint32_t aQlo = aQhi + (S_QLO - S_QHI);
    // K (non-trans, B frag): bit4 -> +8 rows, bit3 -> +16B k-seg
    uint32_t aKhi = sb + S_KHI +
        (uint32_t)(((lane & 7) + ((lane >> 4) & 1) * 8) * AROW + ((lane >> 3) & 1) * 16);
    uint32_t aKlo = aKhi + (S_KLO - S_KHI);
    // V (trans, B frag from [key][d]): bit3 -> +8 rows, bit4 -> +16B n-seg
    uint32_t aVhi = sb + S_VHI +
        (uint32_t)(((lane & 7) + ((lane >> 3) & 1) * 8) * AROW + ((lane >> 4) & 1) * 16);
    uint32_t aVlo = aVhi + (S_VLO - S_VHI);

    float acc[8][4];
    #pragma unroll
    for (int j = 0; j < 8; j++)
        #pragma unroll
        for (int q = 0; q < 4; q++) acc[j][q] = 0.f;
    float mreg[2] = {-1e30f, -1e30f};
    float Sreg[2] = {0.f, 0.f};
    float sqq[2]  = {-1e30f, -1e30f};

    for (int k0 = 0; k0 < C_; k0 += 64) {
        __syncthreads();
        // ---- load K,V tiles (64x64) -> smem hi/lo ----
        #pragma unroll
        for (int i = 0; i < 4; i++) {
            int id = t + i * 256;            // 1024 float4 positions
            int row = id >> 4, c4 = id & 15;
            size_t gro = ((size_t)(b * C_ + k0 + row)) * E_ + h * 64 + c4 * 4;
            float4 kv = *(const float4*)&Kp[gro];
            float4 vv = *(const float4*)&Vp[gro];
            uint32_t h0, l0, h1, l1;
            int off = row * AROW + c4 * 8;
            split2(kv.x, kv.y, h0, l0);
            split2(kv.z, kv.w, h1, l1);
            *(uint2*)(smb + S_KHI + off) = make_uint2(h0, h1);
            *(uint2*)(smb + S_KLO + off) = make_uint2(l0, l1);
            split2(vv.x, vv.y, h0, l0);
            split2(vv.z, vv.w, h1, l1);
            *(uint2*)(smb + S_VHI + off) = make_uint2(h0, h1);
            *(uint2*)(smb + S_VLO + off) = make_uint2(l0, l1);
        }
        __syncthreads();

        // ---- S = scale * Q K^T + mask (split-bf16, 3 terms) ----
        float s[8][4];
        #pragma unroll
        for (int j = 0; j < 8; j++)
            #pragma unroll
            for (int q = 0; q < 4; q++) s[j][q] = 0.f;

        #pragma unroll
        for (int ks = 0; ks < 4; ks++) {
            uint32_t ko = ks * 32;
            uint32_t ah[4], al[4], bf[8][2];
            ldsm4(ah[0], ah[1], ah[2], ah[3], aQhi + ko);
            ldsm4(al[0], al[1], al[2], al[3], aQlo + ko);
            #pragma unroll
            for (int p = 0; p < 4; p++)
                ldsm4(bf[2 * p][0], bf[2 * p][1], bf[2 * p + 1][0], bf[2 * p + 1][1],
                      aKhi + p * (16 * AROW) + ko);
            #pragma unroll
            for (int j = 0; j < 8; j++) mma_bf16(s[j], ah, bf[j]);
            #pragma unroll
            for (int j = 0; j < 8; j++) mma_bf16(s[j], al, bf[j]);
            #pragma unroll
            for (int p = 0; p < 4; p++)
                ldsm4(bf[2 * p][0], bf[2 * p][1], bf[2 * p + 1][0], bf[2 * p + 1][1],
                      aKlo + p * (16 * AROW) + ko);
            #pragma unroll
            for (int j = 0; j < 8; j++) mma_bf16(s[j], ah, bf[j]);
        }

        // ---- scale + mask + capture raw diag score ----
        const float* mr0 = &mask[(size_t)qrow_g * C_ + k0 + (lane & 3) * 2];
        const float* mr1 = mr0 + 8 * C_;
        #pragma unroll
        for (int j = 0; j < 8; j++) {
            float2 m0v = *(const float2*)&mr0[j * 8];
            float2 m1v = *(const float2*)&mr1[j * 8];
            s[j][0] = s[j][0] * scale + m0v.x;
            s[j][1] = s[j][1] * scale + m0v.y;
            s[j][2] = s[j][2] * scale + m1v.x;
            s[j][3] = s[j][3] * scale + m1v.y;
            int cg = k0 + j * 8 + (lane & 3) * 2;
            if (cg     == qrow_g)     sqq[0] = s[j][0];
            if (cg + 1 == qrow_g)     sqq[0] = s[j][1];
            if (cg     == qrow_g + 8) sqq[1] = s[j][2];
            if (cg + 1 == qrow_g + 8) sqq[1] = s[j][3];
        }

        // ---- online softmax on fragments ----
        float tm0 = -1e30f, tm1 = -1e30f;
        #pragma unroll
        for (int j = 0; j < 8; j++) {
            tm0 = fmaxf(tm0, fmaxf(s[j][0], s[j][1]));
            tm1 = fmaxf(tm1, fmaxf(s[j][2], s[j][3]));
        }
        tm0 = fmaxf(tm0, __shfl_xor_sync(0xffffffffu, tm0, 1));
        tm0 = fmaxf(tm0, __shfl_xor_sync(0xffffffffu, tm0, 2));
        tm1 = fmaxf(tm1, __shfl_xor_sync(0xffffffffu, tm1, 1));
        tm1 = fmaxf(tm1, __shfl_xor_sync(0xffffffffu, tm1, 2));
        float mn0 = fmaxf(mreg[0], tm0), mn1 = fmaxf(mreg[1], tm1);
        float al0 = __expf(mreg[0] - mn0), al1 = __expf(mreg[1] - mn1);
        float ps0 = 0.f, ps1 = 0.f;
        #pragma unroll
        for (int j = 0; j < 8; j++) {
            s[j][0] = __expf(s[j][0] - mn0); ps0 += s[j][0];
            s[j][1] = __expf(s[j][1] - mn0); ps0 += s[j][1];
            s[j][2] = __expf(s[j][2] - mn1); ps1 += s[j][2];
            s[j][3] = __expf(s[j][3] - mn1); ps1 += s[j][3];
        }
        ps0 += __shfl_xor_sync(0xffffffffu, ps0, 1);
        ps0 += __shfl_xor_sync(0xffffffffu, ps0, 2);
        ps1 += __shfl_xor_sync(0xffffffffu, ps1, 1);
        ps1 += __shfl_xor_sync(0xffffffffu, ps1, 2);
        Sreg[0] = Sreg[0] * al0 + ps0;  mreg[0] = mn0;
        Sreg[1] = Sreg[1] * al1 + ps1;  mreg[1] = mn1;
        #pragma unroll
        for (int j = 0; j < 8; j++) {
            acc[j][0] *= al0; acc[j][1] *= al0;
            acc[j][2] *= al1; acc[j][3] *= al1;
        }

        // ---- PV: P packed from acc-layout into A frags; V via ldsm.trans ----
        #pragma unroll
        for (int kb = 0; kb < 4; kb++) {
            uint32_t ph[4], pl[4];
            split2(s[2 * kb][0],     s[2 * kb][1],     ph[0], pl[0]);
            split2(s[2 * kb][2],     s[2 * kb][3],     ph[1], pl[1]);
            split2(s[2 * kb + 1][0], s[2 * kb + 1][1], ph[2], pl[2]);
            split2(s[2 * kb + 1][2], s[2 * kb + 1][3], ph[3], pl[3]);
            uint32_t bv[8][2];
            #pragma unroll
            for (int np = 0; np < 4; np++)
                ldsm4t(bv[2 * np][0], bv[2 * np][1], bv[2 * np + 1][0], bv[2 * np + 1][1],
                       aVhi + kb * (16 * AROW) + np * 32);
            #pragma unroll
            for (int j = 0; j < 8; j++) mma_bf16(acc[j], ph, bv[j]);
            #pragma unroll
            for (int j = 0; j < 8; j++) mma_bf16(acc[j], pl, bv[j]);
            #pragma unroll
            for (int np = 0; np < 4; np++)
                ldsm4t(bv[2 * np][0], bv[2 * np][1], bv[2 * np + 1][0], bv[2 * np + 1][1],
                       aVlo + kb * (16 * AROW) + np * 32);
            #pragma unroll
            for (int j = 0; j < 8; j++) mma_bf16(acc[j], ph, bv[j]);
        }
    }

    // ---- epilogue: both outputs ----
    float sq0 = fmaxf(sqq[0], __shfl_xor_sync(0xffffffffu, sqq[0], 1));
    sq0 = fmaxf(sq0, __shfl_xor_sync(0xffffffffu, sq0, 2));
    float sq1 = fmaxf(sqq[1], __shfl_xor_sync(0xffffffffu, sqq[1], 1));
    sq1 = fmaxf(sq1, __shfl_xor_sync(0xffffffffu, sq1, 2));

    float m0 = mreg[0], m1 = mreg[1];
    float eq0 = __expf(sq0 - m0), eq1 = __expf(sq1 - m1);
    float ez0 = __expf(rowz[wrow + qr] - m0);
    float ez1 = __expf(rowz[wrow + qr + 8] - m1);
    float i0 = 1.f / Sreg[0], i1 = 1.f / Sreg[1];
    float iu0 = 1.f / (Sreg[0] - eq0 + ez0);
    float iu1 = 1.f / (Sreg[1] - eq1 + ez1);

    #pragma unroll
    for (int j = 0; j < 8; j++) {
        int dc = j * 8 + (lane & 3) * 2;
        size_t go0 = ((size_t)(b * C_ + qrow_g)) * E_ + h * 64 + dc;
        size_t go1 = go0 + (size_t)8 * E_;
        float2 vq0 = *(const float2*)&Vp[go0];
        float2 vu0 = *(const float2*)&Vup[go0];
        float2 vq1 = *(const float2*)&Vp[go1];
        float2 vu1 = *(const float2*)&Vup[go1];

        *(float2*)&out[go0] = make_float2(acc[j][0] * i0, acc[j][1] * i0);
        *(float2*)&out[go1] = make_float2(acc[j][2] * i1, acc[j][3] * i1);
        *(float2*)&out[(size_t)BCE + go0] = make_float2(
            (acc[j][0] - eq0 * vq0.x + ez0 * vu0.x) * iu0,
            (acc[j][1] - eq0 * vq0.y + ez0 * vu0.y) * iu0);
        *(float2*)&out[(size_t)BCE + go1] = make_float2(
            (acc[j][2] - eq1 * vq1.x + ez1 * vu1.x) * iu1,
            (acc[j][3] - eq1 * vq1.y + ez1 * vu1.y) * iu1);
    }
}

// ---------------------------------------------------------------------------
extern "C" void kernel_launch(void* const* d_in, const int* in_sizes, int n_in,
                              void* d_out, int out_size)
{
    const float* embed   = (const float*)d_in[0];
    const float* embed_u = (const float*)d_in[1];
    const float* mask    = (const float*)d_in[2];
    const float* Wk      = (const float*)d_in[3];
    const float* bk      = (const float*)d_in[4];
    const float* Wq      = (const float*)d_in[5];
    const float* bq      = (const float*)d_in[6];
    const float* Wv      = (const float*)d_in[7];
    const float* bv      = (const float*)d_in[8];
    float* out = (float*)d_out;

    dim3 gg(E_ / 128, (B_ * C_) / 128, 5);
    gemm_tc_kernel<<<gg, 256>>>(embed, embed_u, Wk, Wq, Wv, bk, bq, bv);

    cudaFuncSetAttribute(attn_tc_kernel, cudaFuncAttributeMaxDynamicSharedMemorySize, ATTN_SMEM_B);
    dim3 ga(C_ / 128, B_ * H_);
    attn_tc_kernel<<<ga, 256, ATTN_SMEM_B>>>(mask, out);
}

// round 8
// speedup vs baseline: 2.7109x; 1.0384x over previous
#include <cuda_runtime.h>
#include <cuda_bf16.h>
#include <math.h>
#include <stdint.h>

#define B_ 4
#define C_ 1024
#define E_ 1024
#define H_ 16
#define D_ 64
#define BCE (B_ * C_ * E_)

// fp32 scratch: 0=K, 1=V, 2=Ku, 3=Qu, 4=Vu   (each B*C x E row-major)
__device__ float g_scr[5][B_ * C_ * E_];
// bf16 split scratch: activations [0]=embed, [1]=embed_u;  weights 0=Wk,1=Wq,2=Wv
__device__ __nv_bfloat16 g_ahi[2][BCE], g_alo[2][BCE];
__device__ __nv_bfloat16 g_whi[3][E_ * E_], g_wlo[3][E_ * E_];

// ---------------------------------------------------------------------------
// Common helpers
// ---------------------------------------------------------------------------
__device__ __forceinline__ uint32_t smem_u32(const void* p) {
    uint32_t a;
    asm("{ .reg .u64 t; cvta.to.shared.u64 t, %1; cvt.u32.u64 %0, t; }"
        : "=r"(a) : "l"(p));
    return a;
}
__device__ __forceinline__ void ldsm4(uint32_t& r0, uint32_t& r1, uint32_t& r2,
                                      uint32_t& r3, uint32_t addr) {
    asm volatile("ldmatrix.sync.aligned.m8n8.x4.shared.b16 {%0,%1,%2,%3}, [%4];"
                 : "=r"(r0), "=r"(r1), "=r"(r2), "=r"(r3) : "r"(addr));
}
__device__ __forceinline__ void ldsm4t(uint32_t& r0, uint32_t& r1, uint32_t& r2,
                                       uint32_t& r3, uint32_t addr) {
    asm volatile("ldmatrix.sync.aligned.m8n8.x4.trans.shared.b16 {%0,%1,%2,%3}, [%4];"
                 : "=r"(r0), "=r"(r1), "=r"(r2), "=r"(r3) : "r"(addr));
}
__device__ __forceinline__ void mma_bf16(float* d, const uint32_t* a, const uint32_t* b) {
    asm volatile(
        "mma.sync.aligned.m16n8k16.row.col.f32.bf16.bf16.f32 "
        "{%0,%1,%2,%3}, {%4,%5,%6,%7}, {%8,%9}, {%0,%1,%2,%3};"
        : "+f"(d[0]), "+f"(d[1]), "+f"(d[2]), "+f"(d[3])
        : "r"(a[0]), "r"(a[1]), "r"(a[2]), "r"(a[3]), "r"(b[0]), "r"(b[1]));
}
__device__ __forceinline__ void split2(float x, float y, uint32_t& hi, uint32_t& lo) {
    __nv_bfloat162 h = __floats2bfloat162_rn(x, y);
    hi = *(uint32_t*)&h;
    float lx = x - __bfloat162float(h.x);
    float ly = y - __bfloat162float(h.y);
    __nv_bfloat162 l = __floats2bfloat162_rn(lx, ly);
    lo = *(uint32_t*)&l;
}
__device__ __forceinline__ void cp16(uint32_t dst, const void* src) {
    asm volatile("cp.async.cg.shared.global [%0], [%1], 16;" :: "r"(dst), "l"(src));
}

// ===========================================================================
// Split pre-pass: fp32 -> bf16 hi/lo for embed, embed_u, Wk, Wq, Wv.
// One float4 per thread-index. Boundaries in float4 units.
// ===========================================================================
#define F4_EMB (BCE / 4)          // 1048576
#define F4_W   (E_ * E_ / 4)      // 262144
#define F4_TOT (2 * F4_EMB + 3 * F4_W)

__global__ __launch_bounds__(256) void split_kernel(
    const float* __restrict__ embed, const float* __restrict__ embed_u,
    const float* __restrict__ Wk, const float* __restrict__ Wq,
    const float* __restrict__ Wv)
{
    size_t idx = (size_t)blockIdx.x * 256 + threadIdx.x;
    if (idx >= F4_TOT) return;
    const float* src;
    __nv_bfloat16 *hi, *lo;
    size_t off;
    if (idx < F4_EMB)              { src = embed;   hi = g_ahi[0]; lo = g_alo[0]; off = idx; }
    else if (idx < 2 * F4_EMB)     { src = embed_u; hi = g_ahi[1]; lo = g_alo[1]; off = idx - F4_EMB; }
    else if (idx < 2 * F4_EMB + F4_W)     { src = Wk; hi = g_whi[0]; lo = g_wlo[0]; off = idx - 2 * F4_EMB; }
    else if (idx < 2 * F4_EMB + 2 * F4_W) { src = Wq; hi = g_whi[1]; lo = g_wlo[1]; off = idx - 2 * F4_EMB - F4_W; }
    else                            { src = Wv; hi = g_whi[2]; lo = g_wlo[2]; off = idx - 2 * F4_EMB - 2 * F4_W; }

    float4 v = *(const float4*)&src[off * 4];
    uint32_t h0, l0, h1, l1;
    split2(v.x, v.y, h0, l0);
    split2(v.z, v.w, h1, l1);
    *(uint2*)&hi[off * 4] = make_uint2(h0, h1);
    *(uint2*)&lo[off * 4] = make_uint2(l0, l1);
}

// ===========================================================================
// Pipelined bf16 split GEMM: C[z] = A[z] @ W[z] + b[z]
// 128x128 tile, K-chunk 32, cp.async 2-stage double buffer, 2 CTAs/SM.
// A [m][k] ldsm non-trans; W [k][n] ldsm.trans (no transpose pass).
// ===========================================================================
#define AR 80                       // A smem row stride bytes (64 data + 16 pad)
#define BR 272                      // B smem row stride bytes (256 data + 16 pad)
#define OFF_ALO 10240               // 128*80
#define OFF_BHI 20480
#define OFF_BLO 29184               // 20480 + 32*272
#define STG 37888                   // stage bytes
#define GEMM_DSMEM (2 * STG)
#define NCH 32                      // 1024/32 K-chunks

__global__ __launch_bounds__(256, 2) void gemm_tc_kernel(
    const float* __restrict__ bk, const float* __restrict__ bq,
    const float* __restrict__ bv)
{
    extern __shared__ __align__(1024) char gsm[];
    uint32_t sb = smem_u32(gsm);

    int z = blockIdx.z;
    int ai = (z >= 2) ? 1 : 0;
    int wi = (z == 3) ? 1 : ((z == 1 || z == 4) ? 2 : 0);
    const float* bias = (z == 3) ? bq : ((z == 1 || z == 4) ? bv : bk);
    const __nv_bfloat16* Ah = g_ahi[ai];
    const __nv_bfloat16* Al = g_alo[ai];
    const __nv_bfloat16* Wh = g_whi[wi];
    const __nv_bfloat16* Wl = g_wlo[wi];
    float* Cout = g_scr[z];

    int t = threadIdx.x;
    int lane = t & 31, warp = t >> 5;
    int wm = warp & 1, wn = warp >> 1;       // warp tile (wm*64, wn*32)
    int bm = blockIdx.y * 128;
    int bn = blockIdx.x * 128;

    // per-lane ldsm offsets (within stage)
    uint32_t aoff[4];
    #pragma unroll
    for (int mf = 0; mf < 4; mf++)
        aoff[mf] = (uint32_t)((wm * 64 + mf * 16 + (lane & 15)) * AR + (lane >> 4) * 16);
    uint32_t boff = (uint32_t)(OFF_BHI +
        ((lane & 7) + ((lane >> 3) & 1) * 8) * BR + ((lane >> 4) & 1) * 16 + wn * 64);

    // cp.async issue for chunk c into stage c%2
    auto issue = [&](int c) {
        uint32_t sst = sb + (uint32_t)((c & 1) * STG);
        int k0 = c * 32;
        #pragma unroll
        for (int i = 0; i < 2; i++) {
            int id = t + i * 256;
            int row = id >> 2, c4 = id & 3;
            size_t g = (size_t)(bm + row) * E_ + k0 + c4 * 8;
            uint32_t d = sst + (uint32_t)(row * AR + c4 * 16);
            cp16(d, Ah + g);
            cp16(d + OFF_ALO, Al + g);
        }
        #pragma unroll
        for (int i = 0; i < 2; i++) {
            int id = t + i * 256;
            int kr = id >> 4, cc = id & 15;
            size_t g = (size_t)(k0 + kr) * E_ + bn + cc * 8;
            uint32_t d = sst + (uint32_t)(OFF_BHI + kr * BR + cc * 16);
            cp16(d, Wh + g);
            cp16(d + (OFF_BLO - OFF_BHI), Wl + g);
        }
        asm volatile("cp.async.commit_group;" ::: "memory");
    };

    float acc[4][4][4];
    #pragma unroll
    for (int i = 0; i < 4; i++)
        #pragma unroll
        for (int j = 0; j < 4; j++)
            #pragma unroll
            for (int q = 0; q < 4; q++) acc[i][j][q] = 0.f;

    issue(0);

    for (int c = 0; c < NCH; c++) {
        asm volatile("cp.async.wait_group 0;" ::: "memory");
        __syncthreads();
        if (c + 1 < NCH) issue(c + 1);

        uint32_t st = sb + (uint32_t)((c & 1) * STG);
        #pragma unroll
        for (int kb = 0; kb < 2; kb++) {
            uint32_t kA = kb * 32;            // 16 bf16 = 32B
            uint32_t kB = kb * (16 * BR);     // 16 k-rows
            uint32_t a_h[4][4], a_l[4][4], b_h[4][2], b_l[4][2];
            #pragma unroll
            for (int np = 0; np < 2; np++)
                ldsm4t(b_h[2 * np][0], b_h[2 * np][1], b_h[2 * np + 1][0], b_h[2 * np + 1][1],
                       st + boff + kB + np * 32);
            #pragma unroll
            for (int mf = 0; mf < 4; mf++)
                ldsm4(a_h[mf][0], a_h[mf][1], a_h[mf][2], a_h[mf][3], st + aoff[mf] + kA);
            #pragma unroll
            for (int mf = 0; mf < 4; mf++)
                #pragma unroll
                for (int nf = 0; nf < 4; nf++) mma_bf16(acc[mf][nf], a_h[mf], b_h[nf]);
            #pragma unroll
            for (int mf = 0; mf < 4; mf++)
                ldsm4(a_l[mf][0], a_l[mf][1], a_l[mf][2], a_l[mf][3],
                      st + aoff[mf] + OFF_ALO + kA);
            #pragma unroll
            for (int mf = 0; mf < 4; mf++)
                #pragma unroll
                for (int nf = 0; nf < 4; nf++) mma_bf16(acc[mf][nf], a_l[mf], b_h[nf]);
            #pragma unroll
            for (int np = 0; np < 2; np++)
                ldsm4t(b_l[2 * np][0], b_l[2 * np][1], b_l[2 * np + 1][0], b_l[2 * np + 1][1],
                       st + boff + (OFF_BLO - OFF_BHI) + kB + np * 32);
            #pragma unroll
            for (int mf = 0; mf < 4; mf++)
                #pragma unroll
                for (int nf = 0; nf < 4; nf++) mma_bf16(acc[mf][nf], a_h[mf], b_l[nf]);
        }
    }

    // epilogue: acc + bias -> gmem (fp32)
    #pragma unroll
    for (int mf = 0; mf < 4; mf++) {
        int row0 = bm + wm * 64 + mf * 16 + (lane >> 2);
        #pragma unroll
        for (int nf = 0; nf < 4; nf++) {
            int col = bn + wn * 32 + nf * 8 + (lane & 3) * 2;
            float2 bv2 = *(const float2*)&bias[col];
            float2 o0 = make_float2(acc[mf][nf][0] + bv2.x, acc[mf][nf][1] + bv2.y);
            float2 o1 = make_float2(acc[mf][nf][2] + bv2.x, acc[mf][nf][3] + bv2.y);
            *(float2*)&Cout[(size_t)row0 * E_ + col]       = o0;
            *(float2*)&Cout[(size_t)(row0 + 8) * E_ + col] = o1;
        }
    }
}

// ===========================================================================
// Tensor-core attention (unchanged, known-good)
// ===========================================================================
#define AROW 144
#define S_QHI 0
#define S_QLO 18432
#define S_KHI 36864
#define S_KLO 46080
#define S_VHI 55296
#define S_VLO 64512
#define S_RZ  73728
#define ATTN_SMEM_B (73728 + 512)

__global__ __launch_bounds__(256) void attn_tc_kernel(
    const float* __restrict__ mask, float* __restrict__ out)
{
    extern __shared__ __align__(1024) char smb[];
    uint32_t sb = smem_u32(smb);
    float* rowz = (float*)(smb + S_RZ);

    const float scale = 0.125f;
    int t = threadIdx.x, lane = t & 31, warp = t >> 5;
    int bh = blockIdx.y, b = bh >> 4, h = bh & 15;
    int q0 = blockIdx.x * 128;

    const float* Kp  = g_scr[0];
    const float* Vp  = g_scr[1];
    const float* Kup = g_scr[2];
    const float* Qup = g_scr[3];
    const float* Vup = g_scr[4];

    #pragma unroll
    for (int i = 0; i < 8; i++) {
        int id = t + i * 256;
        int row = id >> 4, c4 = id & 15;
        float4 v = *(const float4*)&Qup[((size_t)(b * C_ + q0 + row)) * E_ + h * 64 + c4 * 4];
        uint32_t h0, l0, h1, l1;
        split2(v.x, v.y, h0, l0);
        split2(v.z, v.w, h1, l1);
        int off = row * AROW + c4 * 8;
        *(uint2*)(smb + S_QHI + off) = make_uint2(h0, h1);
        *(uint2*)(smb + S_QLO + off) = make_uint2(l0, l1);
    }
    {
        int row = t >> 1, part = t & 1;
        int q = q0 + row;
        const float* qp = &Qup[((size_t)(b * C_ + q)) * E_ + h * 64 + part * 32];
        const float* kp = &Kup[((size_t)(b * C_ + q)) * E_ + h * 64 + part * 32];
        float s = 0.f;
        #pragma unroll
        for (int i = 0; i < 8; i++) {
            float4 a = *(const float4*)&qp[i * 4];
            float4 c = *(const float4*)&kp[i * 4];
            s += a.x * c.x + a.y * c.y + a.z * c.z + a.w * c.w;
        }
        s += __shfl_xor_sync(0xffffffffu, s, 1);
        if (part == 0) rowz[row] = s * scale + mask[(size_t)q * C_ + q];
    }
    __syncthreads();

    int wrow = warp * 16;
    int qr = lane >> 2;
    int qrow_g = q0 + wrow + qr;

    uint32_t aQhi = sb + S_QHI + (uint32_t)((wrow + (lane & 15)) * AROW + (lane >> 4) * 16);
    uint32_t aQlo = aQhi + (S_QLO - S_QHI);
    uint32_t aKhi = sb + S_KHI +
        (uint32_t)(((lane & 7) + ((lane >> 4) & 1) * 8) * AROW + ((lane >> 3) & 1) * 16);
    uint32_t aKlo = aKhi + (S_KLO - S_KHI);
    uint32_t aVhi = sb + S_VHI +
        (uint32_t)(((lane & 7) + ((lane >> 3) & 1) * 8) * AROW + ((lane >> 4) & 1) * 16);
    uint32_t aVlo = aVhi + (S_VLO - S_VHI);

    float acc[8][4];
    #pragma unroll
    for (int j = 0; j < 8; j++)
        #pragma unroll
        for (int q = 0; q < 4; q++) acc[j][q] = 0.f;
    float mreg[2] = {-1e30f, -1e30f};
    float Sreg[2] = {0.f, 0.f};
    float sqq[2]  = {-1e30f, -1e30f};

    for (int k0 = 0; k0 < C_; k0 += 64) {
        __syncthreads();
        #pragma unroll
        for (int i = 0; i < 4; i++) {
            int id = t + i * 256;
            int row = id >> 4, c4 = id & 15;
            size_t gro = ((size_t)(b * C_ + k0 + row)) * E_ + h * 64 + c4 * 4;
            float4 kv = *(const float4*)&Kp[gro];
            float4 vv = *(const float4*)&Vp[gro];
            uint32_t h0, l0, h1, l1;
            int off = row * AROW + c4 * 8;
            split2(kv.x, kv.y, h0, l0);
            split2(kv.z, kv.w, h1, l1);
            *(uint2*)(smb + S_KHI + off) = make_uint2(h0, h1);
            *(uint2*)(smb + S_KLO + off) = make_uint2(l0, l1);
            split2(vv.x, vv.y, h0, l0);
            split2(vv.z, vv.w, h1, l1);
            *(uint2*)(smb + S_VHI + off) = make_uint2(h0, h1);
            *(uint2*)(smb + S_VLO + off) = make_uint2(l0, l1);
        }
        __syncthreads();

        float s[8][4];
        #pragma unroll
        for (int j = 0; j < 8; j++)
            #pragma unroll
            for (int q = 0; q < 4; q++) s[j][q] = 0.f;

        #pragma unroll
        for (int ks = 0; ks < 4; ks++) {
            uint32_t ko = ks * 32;
            uint32_t ah[4], al[4], bf[8][2];
            ldsm4(ah[0], ah[1], ah[2], ah[3], aQhi + ko);
            ldsm4(al[0], al[1], al[2], al[3], aQlo + ko);
            #pragma unroll
            for (int p = 0; p < 4; p++)
                ldsm4(bf[2 * p][0], bf[2 * p][1], bf[2 * p + 1][0], bf[2 * p + 1][1],
                      aKhi + p * (16 * AROW) + ko);
            #pragma unroll
            for (int j = 0; j < 8; j++) mma_bf16(s[j], ah, bf[j]);
            #pragma unroll
            for (int j = 0; j < 8; j++) mma_bf16(s[j], al, bf[j]);
            #pragma unroll
            for (int p = 0; p < 4; p++)
                ldsm4(bf[2 * p][0], bf[2 * p][1], bf[2 * p + 1][0], bf[2 * p + 1][1],
                      aKlo + p * (16 * AROW) + ko);
            #pragma unroll
            for (int j = 0; j < 8; j++) mma_bf16(s[j], ah, bf[j]);
        }

        const float* mr0 = &mask[(size_t)qrow_g * C_ + k0 + (lane & 3) * 2];
        const float* mr1 = mr0 + 8 * C_;
        #pragma unroll
        for (int j = 0; j < 8; j++) {
            float2 m0v = *(const float2*)&mr0[j * 8];
            float2 m1v = *(const float2*)&mr1[j * 8];
            s[j][0] = s[j][0] * scale + m0v.x;
            s[j][1] = s[j][1] * scale + m0v.y;
            s[j][2] = s[j][2] * scale + m1v.x;
            s[j][3] = s[j][3] * scale + m1v.y;
            int cg = k0 + j * 8 + (lane & 3) * 2;
            if (cg     == qrow_g)     sqq[0] = s[j][0];
            if (cg + 1 == qrow_g)     sqq[0] = s[j][1];
            if (cg     == qrow_g + 8) sqq[1] = s[j][2];
            if (cg + 1 == qrow_g + 8) sqq[1] = s[j][3];
        }

        float tm0 = -1e30f, tm1 = -1e30f;
        #pragma unroll
        for (int j = 0; j < 8; j++) {
            tm0 = fmaxf(tm0, fmaxf(s[j][0], s[j][1]));
            tm1 = fmaxf(tm1, fmaxf(s[j][2], s[j][3]));
        }
        tm0 = fmaxf(tm0, __shfl_xor_sync(0xffffffffu, tm0, 1));
        tm0 = fmaxf(tm0, __shfl_xor_sync(0xffffffffu, tm0, 2));
        tm1 = fmaxf(tm1, __shfl_xor_sync(0xffffffffu, tm1, 1));
        tm1 = fmaxf(tm1, __shfl_xor_sync(0xffffffffu, tm1, 2));
        float mn0 = fmaxf(mreg[0], tm0), mn1 = fmaxf(mreg[1], tm1);
        float al0 = __expf(mreg[0] - mn0), al1 = __expf(mreg[1] - mn1);
        float ps0 = 0.f, ps1 = 0.f;
        #pragma unroll
        for (int j = 0; j < 8; j++) {
            s[j][0] = __expf(s[j][0] - mn0); ps0 += s[j][0];
            s[j][1] = __expf(s[j][1] - mn0); ps0 += s[j][1];
            s[j][2] = __expf(s[j][2] - mn1); ps1 += s[j][2];
            s[j][3] = __expf(s[j][3] - mn1); ps1 += s[j][3];
        }
        ps0 += __shfl_xor_sync(0xffffffffu, ps0, 1);
        ps0 += __shfl_xor_sync(0xffffffffu, ps0, 2);
        ps1 += __shfl_xor_sync(0xffffffffu, ps1, 1);
        ps1 += __shfl_xor_sync(0xffffffffu, ps1, 2);
        Sreg[0] = Sreg[0] * al0 + ps0;  mreg[0] = mn0;
        Sreg[1] = Sreg[1] * al1 + ps1;  mreg[1] = mn1;
        #pragma unroll
        for (int j = 0; j < 8; j++) {
            acc[j][0] *= al0; acc[j][1] *= al0;
            acc[j][2] *= al1; acc[j][3] *= al1;
        }

        #pragma unroll
        for (int kb = 0; kb < 4; kb++) {
            uint32_t ph[4], pl[4];
            split2(s[2 * kb][0],     s[2 * kb][1],     ph[0], pl[0]);
            split2(s[2 * kb][2],     s[2 * kb][3],     ph[1], pl[1]);
            split2(s[2 * kb + 1][0], s[2 * kb + 1][1], ph[2], pl[2]);
            split2(s[2 * kb + 1][2], s[2 * kb + 1][3], ph[3], pl[3]);
            uint32_t bv[8][2];
            #pragma unroll
            for (int np = 0; np < 4; np++)
                ldsm4t(bv[2 * np][0], bv[2 * np][1], bv[2 * np + 1][0], bv[2 * np + 1][1],
                       aVhi + kb * (16 * AROW) + np * 32);
            #pragma unroll
            for (int j = 0; j < 8; j++) mma_bf16(acc[j], ph, bv[j]);
            #pragma unroll
            for (int j = 0; j < 8; j++) mma_bf16(acc[j], pl, bv[j]);
            #pragma unroll
            for (int np = 0; np < 4; np++)
                ldsm4t(bv[2 * np][0], bv[2 * np][1], bv[2 * np + 1][0], bv[2 * np + 1][1],
                       aVlo + kb * (16 * AROW) + np * 32);
            #pragma unroll
            for (int j = 0; j < 8; j++) mma_bf16(acc[j], ph, bv[j]);
        }
    }

    float sq0 = fmaxf(sqq[0], __shfl_xor_sync(0xffffffffu, sqq[0], 1));
    sq0 = fmaxf(sq0, __shfl_xor_sync(0xffffffffu, sq0, 2));
    float sq1 = fmaxf(sqq[1], __shfl_xor_sync(0xffffffffu, sqq[1], 1));
    sq1 = fmaxf(sq1, __shfl_xor_sync(0xffffffffu, sq1, 2));

    float m0 = mreg[0], m1 = mreg[1];
    float eq0 = __expf(sq0 - m0), eq1 = __expf(sq1 - m1);
    float ez0 = __expf(rowz[wrow + qr] - m0);
    float ez1 = __expf(rowz[wrow + qr + 8] - m1);
    float i0 = 1.f / Sreg[0], i1 = 1.f / Sreg[1];
    float iu0 = 1.f / (Sreg[0] - eq0 + ez0);
    float iu1 = 1.f / (Sreg[1] - eq1 + ez1);

    #pragma unroll
    for (int j = 0; j < 8; j++) {
        int dc = j * 8 + (lane & 3) * 2;
        size_t go0 = ((size_t)(b * C_ + qrow_g)) * E_ + h * 64 + dc;
        size_t go1 = go0 + (size_t)8 * E_;
        float2 vq0 = *(const float2*)&Vp[go0];
        float2 vu0 = *(const float2*)&Vup[go0];
        float2 vq1 = *(const float2*)&Vp[go1];
        float2 vu1 = *(const float2*)&Vup[go1];

        *(float2*)&out[go0] = make_float2(acc[j][0] * i0, acc[j][1] * i0);
        *(float2*)&out[go1] = make_float2(acc[j][2] * i1, acc[j][3] * i1);
        *(float2*)&out[(size_t)BCE + go0] = make_float2(
            (acc[j][0] - eq0 * vq0.x + ez0 * vu0.x) * iu0,
            (acc[j][1] - eq0 * vq0.y + ez0 * vu0.y) * iu0);
        *(float2*)&out[(size_t)BCE + go1] = make_float2(
            (acc[j][2] - eq1 * vq1.x + ez1 * vu1.x) * iu1,
            (acc[j][3] - eq1 * vq1.y + ez1 * vu1.y) * iu1);
    }
}

// ---------------------------------------------------------------------------
extern "C" void kernel_launch(void* const* d_in, const int* in_sizes, int n_in,
                              void* d_out, int out_size)
{
    const float* embed   = (const float*)d_in[0];
    const float* embed_u = (const float*)d_in[1];
    const float* mask    = (const float*)d_in[2];
    const float* Wk      = (const float*)d_in[3];
    const float* bk      = (const float*)d_in[4];
    const float* Wq      = (const float*)d_in[5];
    const float* bq      = (const float*)d_in[6];
    const float* Wv      = (const float*)d_in[7];
    const float* bv      = (const float*)d_in[8];
    float* out = (float*)d_out;

    split_kernel<<<(F4_TOT + 255) / 256, 256>>>(embed, embed_u, Wk, Wq, Wv);

    cudaFuncSetAttribute(gemm_tc_kernel, cudaFuncAttributeMaxDynamicSharedMemorySize, GEMM_DSMEM);
    dim3 gg(E_ / 128, (B_ * C_) / 128, 5);
    gemm_tc_kernel<<<gg, 256, GEMM_DSMEM>>>(bk, bq, bv);

    cudaFuncSetAttribute(attn_tc_kernel, cudaFuncAttributeMaxDynamicSharedMemorySize, ATTN_SMEM_B);
    dim3 ga(C_ / 128, B_ * H_);
    attn_tc_kernel<<<ga, 256, ATTN_SMEM_B>>>(mask, out);
}

// round 9
// speedup vs baseline: 3.2947x; 1.2153x over previous
#include <cuda_runtime.h>
#include <cuda_fp16.h>
#include <math.h>
#include <stdint.h>

#define B_ 4
#define C_ 1024
#define E_ 1024
#define H_ 16
#define D_ 64
#define BCE (B_ * C_ * E_)

// fp32 scratch: 0=K(unused), 1=V, 2=Ku, 3=Qu, 4=Vu
__device__ float g_scr[5][B_ * C_ * E_];
// fp16 split scratch: activations hi/lo; weights hi only
__device__ __half g_ah[2][BCE], g_al[2][BCE];
__device__ __half g_wh[3][E_ * E_];
// fp16 attn inputs (written by GEMM epilogue)
__device__ __half g_kh[BCE], g_vh[BCE], g_qh[BCE], g_ql[BCE];

// ---------------------------------------------------------------------------
// Common helpers
// ---------------------------------------------------------------------------
__device__ __forceinline__ uint32_t smem_u32(const void* p) {
    uint32_t a;
    asm("{ .reg .u64 t; cvta.to.shared.u64 t, %1; cvt.u32.u64 %0, t; }"
        : "=r"(a) : "l"(p));
    return a;
}
__device__ __forceinline__ void ldsm4(uint32_t& r0, uint32_t& r1, uint32_t& r2,
                                      uint32_t& r3, uint32_t addr) {
    asm volatile("ldmatrix.sync.aligned.m8n8.x4.shared.b16 {%0,%1,%2,%3}, [%4];"
                 : "=r"(r0), "=r"(r1), "=r"(r2), "=r"(r3) : "r"(addr));
}
__device__ __forceinline__ void ldsm4t(uint32_t& r0, uint32_t& r1, uint32_t& r2,
                                       uint32_t& r3, uint32_t addr) {
    asm volatile("ldmatrix.sync.aligned.m8n8.x4.trans.shared.b16 {%0,%1,%2,%3}, [%4];"
                 : "=r"(r0), "=r"(r1), "=r"(r2), "=r"(r3) : "r"(addr));
}
__device__ __forceinline__ void mma_f16(float* d, const uint32_t* a, const uint32_t* b) {
    asm volatile(
        "mma.sync.aligned.m16n8k16.row.col.f32.f16.f16.f32 "
        "{%0,%1,%2,%3}, {%4,%5,%6,%7}, {%8,%9}, {%0,%1,%2,%3};"
        : "+f"(d[0]), "+f"(d[1]), "+f"(d[2]), "+f"(d[3])
        : "r"(a[0]), "r"(a[1]), "r"(a[2]), "r"(a[3]), "r"(b[0]), "r"(b[1]));
}
__device__ __forceinline__ void split2h(float x, float y, uint32_t& hi, uint32_t& lo) {
    __half2 h = __floats2half2_rn(x, y);
    hi = *(uint32_t*)&h;
    float lx = x - __low2float(h);
    float ly = y - __high2float(h);
    __half2 l = __floats2half2_rn(lx, ly);
    lo = *(uint32_t*)&l;
}
__device__ __forceinline__ void cp16(uint32_t dst, const void* src) {
    asm volatile("cp.async.cg.shared.global [%0], [%1], 16;" :: "r"(dst), "l"(src));
}

// ===========================================================================
// Split pre-pass: fp32 -> fp16.  embed/embed_u -> hi+lo;  Wk/Wq/Wv -> hi only.
// ===========================================================================
#define F4_EMB (BCE / 4)
#define F4_W   (E_ * E_ / 4)
#define F4_TOT (2 * F4_EMB + 3 * F4_W)

__global__ __launch_bounds__(256) void split_kernel(
    const float* __restrict__ embed, const float* __restrict__ embed_u,
    const float* __restrict__ Wk, const float* __restrict__ Wq,
    const float* __restrict__ Wv)
{
    size_t idx = (size_t)blockIdx.x * 256 + threadIdx.x;
    if (idx >= F4_TOT) return;
    if (idx < 2 * F4_EMB) {
        int ai = idx >= F4_EMB;
        size_t off = idx - (size_t)ai * F4_EMB;
        const float* src = ai ? embed_u : embed;
        float4 v = *(const float4*)&src[off * 4];
        uint32_t h0, l0, h1, l1;
        split2h(v.x, v.y, h0, l0);
        split2h(v.z, v.w, h1, l1);
        *(uint2*)&g_ah[ai][off * 4] = make_uint2(h0, h1);
        *(uint2*)&g_al[ai][off * 4] = make_uint2(l0, l1);
    } else {
        size_t r = idx - 2 * F4_EMB;
        int wi = (int)(r / F4_W);
        size_t off = r - (size_t)wi * F4_W;
        const float* src = (wi == 0) ? Wk : ((wi == 1) ? Wq : Wv);
        float4 v = *(const float4*)&src[off * 4];
        __half2 a = __floats2half2_rn(v.x, v.y);
        __half2 b = __floats2half2_rn(v.z, v.w);
        *(uint2*)&g_wh[wi][off * 4] = make_uint2(*(uint32_t*)&a, *(uint32_t*)&b);
    }
}

// ===========================================================================
// Pipelined fp16 2-term GEMM: C[z] = A[z] @ W[z] + b[z]
// acc = Ah*Wh + Al*Wh.  128x128 tile, K-chunk 32, cp.async double buffer.
// Epilogue writes fp32 scratch + fp16 attn inputs.
// ===========================================================================
#define AR 80
#define OFF_ALO 10240
#define OFF_B 20480
#define BR 272
#define STG 29184                    // 20480 + 32*272
#define GEMM_DSMEM (2 * STG)
#define NCH 32

__global__ __launch_bounds__(256, 2) void gemm_tc_kernel(
    const float* __restrict__ bk, const float* __restrict__ bq,
    const float* __restrict__ bv)
{
    extern __shared__ __align__(1024) char gsm[];
    uint32_t sb = smem_u32(gsm);

    int z = blockIdx.z;
    int ai = (z >= 2) ? 1 : 0;
    int wi = (z == 3) ? 1 : ((z == 1 || z == 4) ? 2 : 0);
    const float* bias = (z == 3) ? bq : ((z == 1 || z == 4) ? bv : bk);
    const __half* Ah = g_ah[ai];
    const __half* Al = g_al[ai];
    const __half* Wh = g_wh[wi];
    float* Cout = g_scr[z];

    int t = threadIdx.x;
    int lane = t & 31, warp = t >> 5;
    int wm = warp & 1, wn = warp >> 1;
    int bm = blockIdx.y * 128;
    int bn = blockIdx.x * 128;

    uint32_t aoff[4];
    #pragma unroll
    for (int mf = 0; mf < 4; mf++)
        aoff[mf] = (uint32_t)((wm * 64 + mf * 16 + (lane & 15)) * AR + (lane >> 4) * 16);
    uint32_t boff = (uint32_t)(OFF_B +
        ((lane & 7) + ((lane >> 3) & 1) * 8) * BR + ((lane >> 4) & 1) * 16 + wn * 64);

    auto issue = [&](int c) {
        uint32_t sst = sb + (uint32_t)((c & 1) * STG);
        int k0 = c * 32;
        #pragma unroll
        for (int i = 0; i < 2; i++) {
            int id = t + i * 256;
            int row = id >> 2, c4 = id & 3;
            size_t g = (size_t)(bm + row) * E_ + k0 + c4 * 8;
            uint32_t d = sst + (uint32_t)(row * AR + c4 * 16);
            cp16(d, Ah + g);
            cp16(d + OFF_ALO, Al + g);
        }
        #pragma unroll
        for (int i = 0; i < 2; i++) {
            int id = t + i * 256;
            int kr = id >> 4, cc = id & 15;
            size_t g = (size_t)(k0 + kr) * E_ + bn + cc * 8;
            cp16(sst + (uint32_t)(OFF_B + kr * BR + cc * 16), Wh + g);
        }
        asm volatile("cp.async.commit_group;" ::: "memory");
    };

    float acc[4][4][4];
    #pragma unroll
    for (int i = 0; i < 4; i++)
        #pragma unroll
        for (int j = 0; j < 4; j++)
            #pragma unroll
            for (int q = 0; q < 4; q++) acc[i][j][q] = 0.f;

    issue(0);

    for (int c = 0; c < NCH; c++) {
        asm volatile("cp.async.wait_group 0;" ::: "memory");
        __syncthreads();
        if (c + 1 < NCH) issue(c + 1);

        uint32_t st = sb + (uint32_t)((c & 1) * STG);
        #pragma unroll
        for (int kb = 0; kb < 2; kb++) {
            uint32_t kA = kb * 32;
            uint32_t kB = kb * (16 * BR);
            uint32_t bh[4][2], af[4][4];
            #pragma unroll
            for (int np = 0; np < 2; np++)
                ldsm4t(bh[2 * np][0], bh[2 * np][1], bh[2 * np + 1][0], bh[2 * np + 1][1],
                       st + boff + kB + np * 32);
            #pragma unroll
            for (int mf = 0; mf < 4; mf++)
                ldsm4(af[mf][0], af[mf][1], af[mf][2], af[mf][3], st + aoff[mf] + kA);
            #pragma unroll
            for (int mf = 0; mf < 4; mf++)
                #pragma unroll
                for (int nf = 0; nf < 4; nf++) mma_f16(acc[mf][nf], af[mf], bh[nf]);
            #pragma unroll
            for (int mf = 0; mf < 4; mf++)
                ldsm4(af[mf][0], af[mf][1], af[mf][2], af[mf][3],
                      st + aoff[mf] + OFF_ALO + kA);
            #pragma unroll
            for (int mf = 0; mf < 4; mf++)
                #pragma unroll
                for (int nf = 0; nf < 4; nf++) mma_f16(acc[mf][nf], af[mf], bh[nf]);
        }
    }

    // epilogue: +bias; fp32 scratch (z!=0) and fp16 attn inputs (z=0,1,3)
    #pragma unroll
    for (int mf = 0; mf < 4; mf++) {
        int row0 = bm + wm * 64 + mf * 16 + (lane >> 2);
        #pragma unroll
        for (int nf = 0; nf < 4; nf++) {
            int col = bn + wn * 32 + nf * 8 + (lane & 3) * 2;
            float2 bv2 = *(const float2*)&bias[col];
            float2 o0 = make_float2(acc[mf][nf][0] + bv2.x, acc[mf][nf][1] + bv2.y);
            float2 o1 = make_float2(acc[mf][nf][2] + bv2.x, acc[mf][nf][3] + bv2.y);
            size_t p0 = (size_t)row0 * E_ + col;
            size_t p1 = (size_t)(row0 + 8) * E_ + col;
            if (z != 0) {
                *(float2*)&Cout[p0] = o0;
                *(float2*)&Cout[p1] = o1;
            }
            if (z == 0) {
                *(__half2*)&g_kh[p0] = __floats2half2_rn(o0.x, o0.y);
                *(__half2*)&g_kh[p1] = __floats2half2_rn(o1.x, o1.y);
            } else if (z == 1) {
                *(__half2*)&g_vh[p0] = __floats2half2_rn(o0.x, o0.y);
                *(__half2*)&g_vh[p1] = __floats2half2_rn(o1.x, o1.y);
            } else if (z == 3) {
                __half2 h0 = __floats2half2_rn(o0.x, o0.y);
                __half2 h1 = __floats2half2_rn(o1.x, o1.y);
                *(__half2*)&g_qh[p0] = h0;
                *(__half2*)&g_qh[p1] = h1;
                *(__half2*)&g_ql[p0] = __floats2half2_rn(o0.x - __low2float(h0),
                                                         o0.y - __high2float(h0));
                *(__half2*)&g_ql[p1] = __floats2half2_rn(o1.x - __low2float(h1),
                                                         o1.y - __high2float(h1));
            }
        }
    }
}

// ===========================================================================
// Tensor-core attention, fp16 2-term, cp.async double-buffered K/V tiles.
// CTA = 128 queries x one (b,h); 8 warps = m16 row blocks; key tiles of 64.
// QK: Qh*Kh + Ql*Kh.   PV: Ph*Vh + Pl*Vh.
// ===========================================================================
#define QROW 144                     // 64 fp16 (128B) + 16B pad
#define S_QH 0
#define S_QL 18432
#define S_KV 36864                   // stages: [Kh 9216 | Vh 9216] x2
#define KVSTG 18432
#define S_RZ 73728
#define ATTN_SMEM_B (73728 + 512)
#define NKT (C_ / 64)

__global__ __launch_bounds__(256) void attn_tc_kernel(
    const float* __restrict__ mask, float* __restrict__ out)
{
    extern __shared__ __align__(1024) char smb[];
    uint32_t sb = smem_u32(smb);
    float* rowz = (float*)(smb + S_RZ);

    const float scale = 0.125f;
    int t = threadIdx.x, lane = t & 31, warp = t >> 5;
    int bh = blockIdx.y, b = bh >> 4, h = bh & 15;
    int q0 = blockIdx.x * 128;

    const float* Vp  = g_scr[1];
    const float* Kup = g_scr[2];
    const float* Qup = g_scr[3];
    const float* Vup = g_scr[4];

    // ---- Q hi/lo -> smem via cp.async ----
    #pragma unroll
    for (int i = 0; i < 4; i++) {
        int id = t + i * 256;                 // 1024 16B positions
        int row = id >> 3, c = id & 7;
        size_t g = (size_t)(b * C_ + q0 + row) * E_ + h * 64 + c * 8;
        uint32_t d = sb + (uint32_t)(S_QH + row * QROW + c * 16);
        cp16(d, g_qh + g);
        cp16(d + (S_QL - S_QH), g_ql + g);
    }
    // ---- K/V tile 0 ----
    auto issueKV = [&](int kt) {
        uint32_t sst = sb + (uint32_t)(S_KV + (kt & 1) * KVSTG);
        int k0 = kt * 64;
        #pragma unroll
        for (int i = 0; i < 2; i++) {
            int id = t + i * 256;             // 512 positions
            int row = id >> 3, c = id & 7;
            size_t g = (size_t)(b * C_ + k0 + row) * E_ + h * 64 + c * 8;
            uint32_t d = sst + (uint32_t)(row * QROW + c * 16);
            cp16(d, g_kh + g);
            cp16(d + 9216, g_vh + g);
        }
        asm volatile("cp.async.commit_group;" ::: "memory");
    };
    issueKV(0);

    // ---- z[q] = scale*<q_u,k_u> + mask[q][q]  (fp32 path) ----
    {
        int row = t >> 1, part = t & 1;
        int q = q0 + row;
        const float* qp = &Qup[((size_t)(b * C_ + q)) * E_ + h * 64 + part * 32];
        const float* kp = &Kup[((size_t)(b * C_ + q)) * E_ + h * 64 + part * 32];
        float s = 0.f;
        #pragma unroll
        for (int i = 0; i < 8; i++) {
            float4 a = *(const float4*)&qp[i * 4];
            float4 c = *(const float4*)&kp[i * 4];
            s += a.x * c.x + a.y * c.y + a.z * c.z + a.w * c.w;
        }
        s += __shfl_xor_sync(0xffffffffu, s, 1);
        if (part == 0) rowz[row] = s * scale + mask[(size_t)q * C_ + q];
    }

    int wrow = warp * 16;
    int qr = lane >> 2;
    int qrow_g = q0 + wrow + qr;

    uint32_t aQh = sb + S_QH + (uint32_t)((wrow + (lane & 15)) * QROW + (lane >> 4) * 16);
    uint32_t aQl = aQh + (S_QL - S_QH);
    uint32_t loffK = (uint32_t)(((lane & 7) + ((lane >> 4) & 1) * 8) * QROW +
                                ((lane >> 3) & 1) * 16);
    uint32_t loffV = (uint32_t)(9216 + ((lane & 7) + ((lane >> 3) & 1) * 8) * QROW +
                                ((lane >> 4) & 1) * 16);

    float acc[8][4];
    #pragma unroll
    for (int j = 0; j < 8; j++)
        #pragma unroll
        for (int q = 0; q < 4; q++) acc[j][q] = 0.f;
    float mreg[2] = {-1e30f, -1e30f};
    float Sreg[2] = {0.f, 0.f};
    float sqq[2]  = {-1e30f, -1e30f};

    for (int kt = 0; kt < NKT; kt++) {
        int k0 = kt * 64;
        asm volatile("cp.async.wait_group 0;" ::: "memory");
        __syncthreads();
        if (kt + 1 < NKT) issueKV(kt + 1);

        uint32_t st = sb + (uint32_t)(S_KV + (kt & 1) * KVSTG);

        // ---- S = scale*Q K^T + mask ----
        float s[8][4];
        #pragma unroll
        for (int j = 0; j < 8; j++)
            #pragma unroll
            for (int q = 0; q < 4; q++) s[j][q] = 0.f;

        #pragma unroll
        for (int ks = 0; ks < 4; ks++) {
            uint32_t ko = ks * 32;
            uint32_t ah[4], al[4], bf[8][2];
            ldsm4(ah[0], ah[1], ah[2], ah[3], aQh + ko);
            ldsm4(al[0], al[1], al[2], al[3], aQl + ko);
            #pragma unroll
            for (int p = 0; p < 4; p++)
                ldsm4(bf[2 * p][0], bf[2 * p][1], bf[2 * p + 1][0], bf[2 * p + 1][1],
                      st + loffK + p * (16 * QROW) + ko);
            #pragma unroll
            for (int j = 0; j < 8; j++) mma_f16(s[j], ah, bf[j]);
            #pragma unroll
            for (int j = 0; j < 8; j++) mma_f16(s[j], al, bf[j]);
        }

        const float* mr0 = &mask[(size_t)qrow_g * C_ + k0 + (lane & 3) * 2];
        const float* mr1 = mr0 + 8 * C_;
        #pragma unroll
        for (int j = 0; j < 8; j++) {
            float2 m0v = *(const float2*)&mr0[j * 8];
            float2 m1v = *(const float2*)&mr1[j * 8];
            s[j][0] = s[j][0] * scale + m0v.x;
            s[j][1] = s[j][1] * scale + m0v.y;
            s[j][2] = s[j][2] * scale + m1v.x;
            s[j][3] = s[j][3] * scale + m1v.y;
            int cg = k0 + j * 8 + (lane & 3) * 2;
            if (cg     == qrow_g)     sqq[0] = s[j][0];
            if (cg + 1 == qrow_g)     sqq[0] = s[j][1];
            if (cg     == qrow_g + 8) sqq[1] = s[j][2];
            if (cg + 1 == qrow_g + 8) sqq[1] = s[j][3];
        }

        // ---- online softmax ----
        float tm0 = -1e30f, tm1 = -1e30f;
        #pragma unroll
        for (int j = 0; j < 8; j++) {
            tm0 = fmaxf(tm0, fmaxf(s[j][0], s[j][1]));
            tm1 = fmaxf(tm1, fmaxf(s[j][2], s[j][3]));
        }
        tm0 = fmaxf(tm0, __shfl_xor_sync(0xffffffffu, tm0, 1));
        tm0 = fmaxf(tm0, __shfl_xor_sync(0xffffffffu, tm0, 2));
        tm1 = fmaxf(tm1, __shfl_xor_sync(0xffffffffu, tm1, 1));
        tm1 = fmaxf(tm1, __shfl_xor_sync(0xffffffffu, tm1, 2));
        float mn0 = fmaxf(mreg[0], tm0), mn1 = fmaxf(mreg[1], tm1);
        float al0 = __expf(mreg[0] - mn0), al1 = __expf(mreg[1] - mn1);
        float ps0 = 0.f, ps1 = 0.f;
        #pragma unroll
        for (int j = 0; j < 8; j++) {
            s[j][0] = __expf(s[j][0] - mn0); ps0 += s[j][0];
            s[j][1] = __expf(s[j][1] - mn0); ps0 += s[j][1];
            s[j][2] = __expf(s[j][2] - mn1); ps1 += s[j][2];
            s[j][3] = __expf(s[j][3] - mn1); ps1 += s[j][3];
        }
        ps0 += __shfl_xor_sync(0xffffffffu, ps0, 1);
        ps0 += __shfl_xor_sync(0xffffffffu, ps0, 2);
        ps1 += __shfl_xor_sync(0xffffffffu, ps1, 1);
        ps1 += __shfl_xor_sync(0xffffffffu, ps1, 2);
        Sreg[0] = Sreg[0] * al0 + ps0;  mreg[0] = mn0;
        Sreg[1] = Sreg[1] * al1 + ps1;  mreg[1] = mn1;
        #pragma unroll
        for (int j = 0; j < 8; j++) {
            acc[j][0] *= al0; acc[j][1] *= al0;
            acc[j][2] *= al1; acc[j][3] *= al1;
        }

        // ---- PV: P hi/lo x V hi ----
        #pragma unroll
        for (int kb = 0; kb < 4; kb++) {
            uint32_t ph[4], pl[4];
            split2h(s[2 * kb][0],     s[2 * kb][1],     ph[0], pl[0]);
            split2h(s[2 * kb][2],     s[2 * kb][3],     ph[1], pl[1]);
            split2h(s[2 * kb + 1][0], s[2 * kb + 1][1], ph[2], pl[2]);
            split2h(s[2 * kb + 1][2], s[2 * kb + 1][3], ph[3], pl[3]);
            uint32_t bv[8][2];
            #pragma unroll
            for (int np = 0; np < 4; np++)
                ldsm4t(bv[2 * np][0], bv[2 * np][1], bv[2 * np + 1][0], bv[2 * np + 1][1],
                       st + loffV + kb * (16 * QROW) + np * 32);
            #pragma unroll
            for (int j = 0; j < 8; j++) mma_f16(acc[j], ph, bv[j]);
            #pragma unroll
            for (int j = 0; j < 8; j++) mma_f16(acc[j], pl, bv[j]);
        }
    }

    // ---- epilogue: both outputs ----
    float sq0 = fmaxf(sqq[0], __shfl_xor_sync(0xffffffffu, sqq[0], 1));
    sq0 = fmaxf(sq0, __shfl_xor_sync(0xffffffffu, sq0, 2));
    float sq1 = fmaxf(sqq[1], __shfl_xor_sync(0xffffffffu, sqq[1], 1));
    sq1 = fmaxf(sq1, __shfl_xor_sync(0xffffffffu, sq1, 2));

    float m0 = mreg[0], m1 = mreg[1];
    float eq0 = __expf(sq0 - m0), eq1 = __expf(sq1 - m1);
    float ez0 = __expf(rowz[wrow + qr] - m0);
    float ez1 = __expf(rowz[wrow + qr + 8] - m1);
    float i0 = 1.f / Sreg[0], i1 = 1.f / Sreg[1];
    float iu0 = 1.f / (Sreg[0] - eq0 + ez0);
    float iu1 = 1.f / (Sreg[1] - eq1 + ez1);

    #pragma unroll
    for (int j = 0; j < 8; j++) {
        int dc = j * 8 + (lane & 3) * 2;
        size_t go0 = ((size_t)(b * C_ + qrow_g)) * E_ + h * 64 + dc;
        size_t go1 = go0 + (size_t)8 * E_;
        float2 vq0 = *(const float2*)&Vp[go0];
        float2 vu0 = *(const float2*)&Vup[go0];
        float2 vq1 = *(const float2*)&Vp[go1];
        float2 vu1 = *(const float2*)&Vup[go1];

        *(float2*)&out[go0] = make_float2(acc[j][0] * i0, acc[j][1] * i0);
        *(float2*)&out[go1] = make_float2(acc[j][2] * i1, acc[j][3] * i1);
        *(float2*)&out[(size_t)BCE + go0] = make_float2(
            (acc[j][0] - eq0 * vq0.x + ez0 * vu0.x) * iu0,
            (acc[j][1] - eq0 * vq0.y + ez0 * vu0.y) * iu0);
        *(float2*)&out[(size_t)BCE + go1] = make_float2(
            (acc[j][2] - eq1 * vq1.x + ez1 * vu1.x) * iu1,
            (acc[j][3] - eq1 * vq1.y + ez1 * vu1.y) * iu1);
    }
}

// ---------------------------------------------------------------------------
extern "C" void kernel_launch(void* const* d_in, const int* in_sizes, int n_in,
                              void* d_out, int out_size)
{
    const float* embed   = (const float*)d_in[0];
    const float* embed_u = (const float*)d_in[1];
    const float* mask    = (const float*)d_in[2];
    const float* Wk      = (const float*)d_in[3];
    const float* bk      = (const float*)d_in[4];
    const float* Wq      = (const float*)d_in[5];
    const float* bq      = (const float*)d_in[6];
    const float* Wv      = (const float*)d_in[7];
    const float* bv      = (const float*)d_in[8];
    float* out = (float*)d_out;

    split_kernel<<<(F4_TOT + 255) / 256, 256>>>(embed, embed_u, Wk, Wq, Wv);

    cudaFuncSetAttribute(gemm_tc_kernel, cudaFuncAttributeMaxDynamicSharedMemorySize, GEMM_DSMEM);
    dim3 gg(E_ / 128, (B_ * C_) / 128, 5);
    gemm_tc_kernel<<<gg, 256, GEMM_DSMEM>>>(bk, bq, bv);

    cudaFuncSetAttribute(attn_tc_kernel, cudaFuncAttributeMaxDynamicSharedMemorySize, ATTN_SMEM_B);
    dim3 ga(C_ / 128, B_ * H_);
    attn_tc_kernel<<<ga, 256, ATTN_SMEM_B>>>(mask, out);
}